// round 1
// baseline (speedup 1.0000x reference)
#include <cuda_runtime.h>
#include <cfloat>
#include <cstdint>

// ---------------------------------------------------------------------------
// Problem-size constants (fixed by the dataset; runtime values derived from
// in_sizes and guarded, but scratch is sized to these maxima).
// ---------------------------------------------------------------------------
#define N_NODE_MAX 500000
#define N_EDGE_MAX 1000000
#define NREL_MAX   512
#define BATCH_MAX  64

#define ENC_NEGINF 0x007FFFFFu

// ---------------------------------------------------------------------------
// Device scratch (static __device__ arrays — no allocation at launch time)
// ---------------------------------------------------------------------------
__device__ unsigned g_agg_enc[(size_t)N_NODE_MAX * 64];  // encoded segment-max
__device__ float    g_node_msg[(size_t)N_NODE_MAX * 64]; // agg@M + Wnode_b
__device__ float    g_s0[N_NODE_MAX];
__device__ float    g_s1[N_NODE_MAX];
__device__ float    g_scores[N_EDGE_MAX];
__device__ float    g_Mext[64 * 66];                      // [k][c]: c<64 -> M, 64->v0, 65->v1
__device__ float    g_crel[NREL_MAX * 8];                 // rela@Wr, padded stride 8
__device__ float    g_cq[BATCH_MAX * 8];                  // rela[q_rel]@Wqr + Wqr_b
__device__ unsigned g_max_enc;
__device__ float    g_sum;

// ---------------------------------------------------------------------------
// Order-preserving float <-> uint encoding (for atomicMax on floats)
// ---------------------------------------------------------------------------
__device__ __forceinline__ unsigned encf(float x) {
    unsigned u = __float_as_uint(x);
    return (u & 0x80000000u) ? ~u : (u | 0x80000000u);
}
__device__ __forceinline__ float decf(unsigned u) {
    return (u & 0x80000000u) ? __uint_as_float(u & 0x7FFFFFFFu)
                             : __uint_as_float(~u);
}

// ---------------------------------------------------------------------------
// K0: setup — precompute M_ext = [Wh@Wnode | Wh@w0 | Wh@w1], crel, cq
// ---------------------------------------------------------------------------
__global__ void k_setup(const float* __restrict__ Wh,
                        const float* __restrict__ Wnode,
                        const float* __restrict__ attn_w,   // (128,1)
                        const float* __restrict__ rela,
                        const float* __restrict__ Wr,
                        const float* __restrict__ Wqr_w,
                        const float* __restrict__ Wqr_b,
                        const int*   __restrict__ q_rel,
                        int nrel, int batch)
{
    int gtid   = blockIdx.x * blockDim.x + threadIdx.x;
    int stride = gridDim.x * blockDim.x;

    for (int i = gtid; i < 64 * 66; i += stride) {
        int k = i / 66, c = i % 66;
        float s = 0.f;
        if (c < 64) {
            #pragma unroll 8
            for (int j = 0; j < 64; j++) s += Wh[k * 64 + j] * Wnode[j * 64 + c];
        } else {
            const float* w = attn_w + (c - 64) * 64;
            #pragma unroll 8
            for (int j = 0; j < 64; j++) s += Wh[k * 64 + j] * w[j];
        }
        g_Mext[i] = s;
    }
    for (int i = gtid; i < nrel * 5; i += stride) {
        int r = i / 5, j = i % 5;
        float s = 0.f;
        #pragma unroll 8
        for (int k = 0; k < 64; k++) s += rela[r * 64 + k] * Wr[k * 5 + j];
        g_crel[r * 8 + j] = s;
    }
    for (int i = gtid; i < batch * 5; i += stride) {
        int b = i / 5, j = i % 5;
        int qr = q_rel[b];
        float s = Wqr_b[j];
        #pragma unroll 8
        for (int k = 0; k < 64; k++) s += rela[qr * 64 + k] * Wqr_w[k * 5 + j];
        g_cq[b * 8 + j] = s;
    }
}

// ---------------------------------------------------------------------------
// K1: init — agg_enc := enc(-inf), out := 0, global max/sum scalars
// ---------------------------------------------------------------------------
__global__ void k_init(float* __restrict__ out, int agg_elems, int out_elems)
{
    size_t i      = (size_t)blockIdx.x * blockDim.x + threadIdx.x;
    size_t stride = (size_t)gridDim.x * blockDim.x;

    uint4*  ap = reinterpret_cast<uint4*>(g_agg_enc);
    float4* op = reinterpret_cast<float4*>(out);
    size_t  na = (size_t)agg_elems >> 2;
    size_t  no = (size_t)out_elems >> 2;
    uint4   ev = make_uint4(ENC_NEGINF, ENC_NEGINF, ENC_NEGINF, ENC_NEGINF);
    float4  zv = make_float4(0.f, 0.f, 0.f, 0.f);

    for (size_t t = i; t < na; t += stride) ap[t] = ev;
    for (size_t t = i; t < no; t += stride) op[t] = zv;
    if (i == 0) { g_max_enc = 0u; g_sum = 0.f; }
}

// ---------------------------------------------------------------------------
// K2: edge pass 1 — alpha-weighted message + segment-max (warp per edge,
//     grid-stride so per-lane Ws registers amortize)
// ---------------------------------------------------------------------------
__global__ void __launch_bounds__(256)
k_edge1(const float* __restrict__ hidden,
        const float* __restrict__ rela,
        const float* __restrict__ Ws,       // (64,5)
        const float* __restrict__ wa,       // (5,1)
        const float* __restrict__ wab,      // (1,)
        const int*   __restrict__ edges,
        int n_edge)
{
    const int lane = threadIdx.x & 31;

    // Per-lane slice of Ws: this lane owns feature dims (2*lane, 2*lane+1)
    float wsa[5], wsb[5], wal[5];
    #pragma unroll
    for (int j = 0; j < 5; j++) {
        wsa[j] = __ldg(Ws + (2 * lane) * 5 + j);
        wsb[j] = __ldg(Ws + (2 * lane + 1) * 5 + j);
        wal[j] = __ldg(wa + j);
    }
    const float walb = __ldg(wab);

    const int warps_total = gridDim.x * (blockDim.x >> 5);
    int w = blockIdx.x * (blockDim.x >> 5) + (threadIdx.x >> 5);

    for (int e = w; e < n_edge; e += warps_total) {
        const int* ep = edges + (size_t)e * 6;
        int2 i01 = *reinterpret_cast<const int2*>(ep);       // r_idx, _
        int2 i23 = *reinterpret_cast<const int2*>(ep + 2);   // rel, _
        int2 i45 = *reinterpret_cast<const int2*>(ep + 4);   // sub, obj
        const int r_idx = i01.x, rel = i23.x, sub = i45.x, obj = i45.y;

        const float2 hs = *reinterpret_cast<const float2*>(hidden + (size_t)sub * 64 + 2 * lane);
        const float2 hr = *reinterpret_cast<const float2*>(rela   + (size_t)rel * 64 + 2 * lane);

        float p0 = hs.x * wsa[0] + hs.y * wsb[0];
        float p1 = hs.x * wsa[1] + hs.y * wsb[1];
        float p2 = hs.x * wsa[2] + hs.y * wsb[2];
        float p3 = hs.x * wsa[3] + hs.y * wsb[3];
        float p4 = hs.x * wsa[4] + hs.y * wsb[4];
        #pragma unroll
        for (int off = 16; off > 0; off >>= 1) {
            p0 += __shfl_xor_sync(0xFFFFFFFFu, p0, off);
            p1 += __shfl_xor_sync(0xFFFFFFFFu, p1, off);
            p2 += __shfl_xor_sync(0xFFFFFFFFu, p2, off);
            p3 += __shfl_xor_sync(0xFFFFFFFFu, p3, off);
            p4 += __shfl_xor_sync(0xFFFFFFFFu, p4, off);
        }

        const float4 c4 = *reinterpret_cast<const float4*>(g_crel + rel * 8);
        const float  c5 = g_crel[rel * 8 + 4];
        const float4 q4 = *reinterpret_cast<const float4*>(g_cq + r_idx * 8);
        const float  q5 = g_cq[r_idx * 8 + 4];

        float z = walb;
        z += fmaxf(p0 + c4.x + q4.x, 0.f) * wal[0];
        z += fmaxf(p1 + c4.y + q4.y, 0.f) * wal[1];
        z += fmaxf(p2 + c4.z + q4.z, 0.f) * wal[2];
        z += fmaxf(p3 + c4.w + q4.w, 0.f) * wal[3];
        z += fmaxf(p4 + c5   + q5,   0.f) * wal[4];
        const float alpha = 1.f / (1.f + expf(-z));

        unsigned* ap = g_agg_enc + (size_t)obj * 64 + 2 * lane;
        atomicMax(ap,     encf(alpha * (hs.x - hr.x)));
        atomicMax(ap + 1, encf(alpha * (hs.y - hr.y)));
    }
}

// ---------------------------------------------------------------------------
// K3: node GEMM — node_msg = dec(agg)@M + Wnode_b; s0 = dec(agg)·v0; s1 = ·v1
//     Block: 64 rows x 66 cols, 256 threads, 4x4 register tiles.
// ---------------------------------------------------------------------------
__global__ void __launch_bounds__(256)
k_gemm(int n_node, const float* __restrict__ Wnode_b)
{
    __shared__ float Ms[64 * 68];   // [k][c], padded
    __shared__ float As[64 * 68];   // [row][k], padded

    const int tid = threadIdx.x;
    for (int i = tid; i < 64 * 66; i += 256)
        Ms[(i / 66) * 68 + (i % 66)] = g_Mext[i];

    const int rb = blockIdx.x * 64;
    #pragma unroll
    for (int t = 0; t < 16; t++) {
        int idx = tid + t * 256;           // 0..4095
        int r = idx >> 6, k = idx & 63;
        int grow = rb + r;
        float v = 0.f;
        if (grow < n_node) {
            unsigned u = g_agg_enc[(size_t)grow * 64 + k];
            v = (u == ENC_NEGINF) ? 0.f : decf(u);
        }
        As[r * 68 + k] = v;
    }
    __syncthreads();

    const int tx = tid & 15;     // col group (4 cols)
    const int ty = tid >> 4;     // row group (4 rows)

    float acc[4][4];
    #pragma unroll
    for (int i = 0; i < 4; i++)
        #pragma unroll
        for (int c = 0; c < 4; c++) acc[i][c] = 0.f;

    #pragma unroll 8
    for (int k = 0; k < 64; k++) {
        const float4 m = *reinterpret_cast<const float4*>(Ms + k * 68 + tx * 4);
        #pragma unroll
        for (int i = 0; i < 4; i++) {
            const float a = As[(ty * 4 + i) * 68 + k];
            acc[i][0] += a * m.x;
            acc[i][1] += a * m.y;
            acc[i][2] += a * m.z;
            acc[i][3] += a * m.w;
        }
    }

    const float4 b4 = *reinterpret_cast<const float4*>(Wnode_b + tx * 4);
    #pragma unroll
    for (int i = 0; i < 4; i++) {
        int grow = rb + ty * 4 + i;
        if (grow < n_node) {
            float4 o = make_float4(acc[i][0] + b4.x, acc[i][1] + b4.y,
                                   acc[i][2] + b4.z, acc[i][3] + b4.w);
            *reinterpret_cast<float4*>(g_node_msg + (size_t)grow * 64 + tx * 4) = o;
        }
    }

    // s0/s1 epilogue: one row per thread (first 64 threads)
    if (tid < 64) {
        int grow = rb + tid;
        if (grow < n_node) {
            float s0 = 0.f, s1 = 0.f;
            #pragma unroll 8
            for (int k = 0; k < 64; k++) {
                const float a = As[tid * 68 + k];
                s0 += a * Ms[k * 68 + 64];
                s1 += a * Ms[k * 68 + 65];
            }
            g_s0[grow] = s0;
            g_s1[grow] = s1;
        }
    }
}

// ---------------------------------------------------------------------------
// K4: edge scores + global max
// ---------------------------------------------------------------------------
__global__ void __launch_bounds__(256)
k_score(const int* __restrict__ edges, const float* __restrict__ attn_b, int n_edge)
{
    const int e = blockIdx.x * 256 + threadIdx.x;
    float sc = -FLT_MAX;
    if (e < n_edge) {
        int2 so = *reinterpret_cast<const int2*>(edges + (size_t)e * 6 + 4);
        float s = g_s0[so.x] + g_s1[so.y] + __ldg(attn_b);
        sc = (s > 0.f) ? s : 0.2f * s;
        g_scores[e] = sc;
    }
    // block-reduce max
    __shared__ float red[8];
    const int lane = threadIdx.x & 31, wid = threadIdx.x >> 5;
    #pragma unroll
    for (int off = 16; off > 0; off >>= 1)
        sc = fmaxf(sc, __shfl_xor_sync(0xFFFFFFFFu, sc, off));
    if (lane == 0) red[wid] = sc;
    __syncthreads();
    if (wid == 0) {
        float v = (lane < 8) ? red[lane] : -FLT_MAX;
        #pragma unroll
        for (int off = 4; off > 0; off >>= 1)
            v = fmaxf(v, __shfl_xor_sync(0xFFFFFFFFu, v, off));
        if (lane == 0) atomicMax(&g_max_enc, encf(v));
    }
}

// ---------------------------------------------------------------------------
// K5: exp(score - max) in place + global sum
// ---------------------------------------------------------------------------
__global__ void __launch_bounds__(256)
k_expsum(int n_edge)
{
    const float gm = decf(g_max_enc);
    const int e = blockIdx.x * 256 + threadIdx.x;
    float v = 0.f;
    if (e < n_edge) {
        v = expf(g_scores[e] - gm);
        g_scores[e] = v;
    }
    __shared__ float red[8];
    const int lane = threadIdx.x & 31, wid = threadIdx.x >> 5;
    #pragma unroll
    for (int off = 16; off > 0; off >>= 1)
        v += __shfl_xor_sync(0xFFFFFFFFu, v, off);
    if (lane == 0) red[wid] = v;
    __syncthreads();
    if (wid == 0) {
        float s = (lane < 8) ? red[lane] : 0.f;
        #pragma unroll
        for (int off = 4; off > 0; off >>= 1)
            s += __shfl_xor_sync(0xFFFFFFFFu, s, off);
        if (lane == 0) atomicAdd(&g_sum, s);
    }
}

// ---------------------------------------------------------------------------
// K6: final weighted scatter — out[sub] += w_e * node_msg[obj] (warp per edge)
// ---------------------------------------------------------------------------
__global__ void __launch_bounds__(256)
k_final(const int* __restrict__ edges, float* __restrict__ out, int n_edge)
{
    const float inv = 1.f / g_sum;
    const int lane = threadIdx.x & 31;
    const int warps_total = gridDim.x * (blockDim.x >> 5);
    int w = blockIdx.x * (blockDim.x >> 5) + (threadIdx.x >> 5);

    for (int e = w; e < n_edge; e += warps_total) {
        int2 so = *reinterpret_cast<const int2*>(edges + (size_t)e * 6 + 4);
        const float wgt = g_scores[e] * inv;
        const float2 m = *reinterpret_cast<const float2*>(g_node_msg + (size_t)so.y * 64 + 2 * lane);
        float* op = out + (size_t)so.x * 64 + 2 * lane;
        atomicAdd(op,     wgt * m.x);
        atomicAdd(op + 1, wgt * m.y);
    }
}

// ---------------------------------------------------------------------------
// kernel_launch
// ---------------------------------------------------------------------------
extern "C" void kernel_launch(void* const* d_in, const int* in_sizes, int n_in,
                              void* d_out, int out_size)
{
    const float* hidden    = (const float*)d_in[0];
    const float* rela      = (const float*)d_in[1];
    const float* Ws        = (const float*)d_in[2];
    const float* Wr        = (const float*)d_in[3];
    const float* Wqr_w     = (const float*)d_in[4];
    const float* Wqr_b     = (const float*)d_in[5];
    const float* walpha_w  = (const float*)d_in[6];
    const float* walpha_b  = (const float*)d_in[7];
    const float* Wh        = (const float*)d_in[8];
    const float* attn_fc_w = (const float*)d_in[9];
    const float* attn_fc_b = (const float*)d_in[10];
    const float* Wnode_w   = (const float*)d_in[11];
    const float* Wnode_b   = (const float*)d_in[12];
    const int*   q_rel     = (const int*)d_in[14];
    const int*   edges     = (const int*)d_in[15];
    float*       out       = (float*)d_out;

    const int n_edge = in_sizes[15] / 6;
    const int n_node = in_sizes[16] / 2;
    const int nrel   = in_sizes[1] / 64;
    const int batch  = in_sizes[14];

    // K0: precompute small tables
    k_setup<<<32, 256>>>(Wh, Wnode_w, attn_fc_w, rela, Wr, Wqr_w, Wqr_b,
                         q_rel, nrel, batch);

    // K1: init scratch + output
    k_init<<<4096, 256>>>(out, n_node * 64, out_size);

    // K2: edge messages + segment max
    k_edge1<<<2368, 256>>>(hidden, rela, Ws, walpha_w, walpha_b, edges, n_edge);

    // K3: fused node GEMM (node_msg, s0, s1)
    k_gemm<<<(n_node + 63) / 64, 256>>>(n_node, Wnode_b);

    // K4/K5: softmax statistics
    k_score<<<(n_edge + 255) / 256, 256>>>(edges, attn_fc_b, n_edge);
    k_expsum<<<(n_edge + 255) / 256, 256>>>(n_edge);

    // K6: weighted scatter to output
    k_final<<<2368, 256>>>(edges, out, n_edge);
}

// round 2
// speedup vs baseline: 1.1170x; 1.1170x over previous
#include <cuda_runtime.h>
#include <cfloat>
#include <cstdint>

// ---------------------------------------------------------------------------
// Problem-size constants
// ---------------------------------------------------------------------------
#define N_NODE_MAX 500000
#define N_EDGE_MAX 1000000
#define NREL_MAX   512
#define BATCH_MAX  64

#define ENC_NEGINF 0x007FFFFFu

// ---------------------------------------------------------------------------
// Device scratch
// ---------------------------------------------------------------------------
__device__ unsigned g_agg_enc[(size_t)N_NODE_MAX * 64];  // encoded segment-max
__device__ float    g_node_msg[(size_t)N_NODE_MAX * 64]; // agg@M + Wnode_b
__device__ float    g_s0[N_NODE_MAX];
__device__ float    g_s1[N_NODE_MAX];
__device__ float    g_scores[N_EDGE_MAX];
__device__ float    g_Mext[64 * 66];                      // [k][c]: c<64 -> M, 64->v0, 65->v1
__device__ float    g_crel[NREL_MAX * 8];                 // rela@Wr, padded stride 8
__device__ float    g_cq[BATCH_MAX * 8];                  // rela[q_rel]@Wqr + Wqr_b
__device__ unsigned g_max_enc;
__device__ float    g_sum;

// ---------------------------------------------------------------------------
// Order-preserving float <-> uint encoding (for atomicMax on floats)
// ---------------------------------------------------------------------------
__device__ __forceinline__ unsigned encf(float x) {
    unsigned u = __float_as_uint(x);
    return (u & 0x80000000u) ? ~u : (u | 0x80000000u);
}
__device__ __forceinline__ float decf(unsigned u) {
    return (u & 0x80000000u) ? __uint_as_float(u & 0x7FFFFFFFu)
                             : __uint_as_float(~u);
}
__device__ __forceinline__ float dec0(unsigned u) {   // decode, -inf -> 0
    return (u == ENC_NEGINF) ? 0.f : decf(u);
}

// ---------------------------------------------------------------------------
// K0: setup — precompute M_ext = [Wh@Wnode | Wh@w0 | Wh@w1], crel, cq
// ---------------------------------------------------------------------------
__global__ void k_setup(const float* __restrict__ Wh,
                        const float* __restrict__ Wnode,
                        const float* __restrict__ attn_w,   // (128,1)
                        const float* __restrict__ rela,
                        const float* __restrict__ Wr,
                        const float* __restrict__ Wqr_w,
                        const float* __restrict__ Wqr_b,
                        const int*   __restrict__ q_rel,
                        int nrel, int batch)
{
    int gtid   = blockIdx.x * blockDim.x + threadIdx.x;
    int stride = gridDim.x * blockDim.x;

    for (int i = gtid; i < 64 * 66; i += stride) {
        int k = i / 66, c = i % 66;
        float s = 0.f;
        if (c < 64) {
            #pragma unroll 8
            for (int j = 0; j < 64; j++) s += Wh[k * 64 + j] * Wnode[j * 64 + c];
        } else {
            const float* w = attn_w + (c - 64) * 64;
            #pragma unroll 8
            for (int j = 0; j < 64; j++) s += Wh[k * 64 + j] * w[j];
        }
        g_Mext[i] = s;
    }
    for (int i = gtid; i < nrel * 5; i += stride) {
        int r = i / 5, j = i % 5;
        float s = 0.f;
        #pragma unroll 8
        for (int k = 0; k < 64; k++) s += rela[r * 64 + k] * Wr[k * 5 + j];
        g_crel[r * 8 + j] = s;
    }
    for (int i = gtid; i < batch * 5; i += stride) {
        int b = i / 5, j = i % 5;
        int qr = q_rel[b];
        float s = Wqr_b[j];
        #pragma unroll 8
        for (int k = 0; k < 64; k++) s += rela[qr * 64 + k] * Wqr_w[k * 5 + j];
        g_cq[b * 8 + j] = s;
    }
}

// ---------------------------------------------------------------------------
// K1: init — agg_enc := enc(-inf), out := 0, global max/sum scalars
// ---------------------------------------------------------------------------
__global__ void k_init(float* __restrict__ out, int agg_elems, int out_elems)
{
    size_t i      = (size_t)blockIdx.x * blockDim.x + threadIdx.x;
    size_t stride = (size_t)gridDim.x * blockDim.x;

    uint4*  ap = reinterpret_cast<uint4*>(g_agg_enc);
    float4* op = reinterpret_cast<float4*>(out);
    size_t  na = (size_t)agg_elems >> 2;
    size_t  no = (size_t)out_elems >> 2;
    uint4   ev = make_uint4(ENC_NEGINF, ENC_NEGINF, ENC_NEGINF, ENC_NEGINF);
    float4  zv = make_float4(0.f, 0.f, 0.f, 0.f);

    for (size_t t = i; t < na; t += stride) ap[t] = ev;
    for (size_t t = i; t < no; t += stride) op[t] = zv;
    if (i == 0) { g_max_enc = 0u; g_sum = 0.f; }
}

// ---------------------------------------------------------------------------
// K2: edge pass 1 — alpha-weighted message + segment-max (warp per edge)
// ---------------------------------------------------------------------------
__global__ void __launch_bounds__(256)
k_edge1(const float* __restrict__ hidden,
        const float* __restrict__ rela,
        const float* __restrict__ Ws,       // (64,5)
        const float* __restrict__ wa,       // (5,1)
        const float* __restrict__ wab,      // (1,)
        const int*   __restrict__ edges,
        int n_edge)
{
    const int lane = threadIdx.x & 31;

    float wsa[5], wsb[5], wal[5];
    #pragma unroll
    for (int j = 0; j < 5; j++) {
        wsa[j] = __ldg(Ws + (2 * lane) * 5 + j);
        wsb[j] = __ldg(Ws + (2 * lane + 1) * 5 + j);
        wal[j] = __ldg(wa + j);
    }
    const float walb = __ldg(wab);

    const int warps_total = gridDim.x * (blockDim.x >> 5);
    int w = blockIdx.x * (blockDim.x >> 5) + (threadIdx.x >> 5);

    for (int e = w; e < n_edge; e += warps_total) {
        const int* ep = edges + (size_t)e * 6;
        int2 i01 = *reinterpret_cast<const int2*>(ep);       // r_idx, _
        int2 i23 = *reinterpret_cast<const int2*>(ep + 2);   // rel, _
        int2 i45 = *reinterpret_cast<const int2*>(ep + 4);   // sub, obj
        const int r_idx = i01.x, rel = i23.x, sub = i45.x, obj = i45.y;

        const float2 hs = *reinterpret_cast<const float2*>(hidden + (size_t)sub * 64 + 2 * lane);
        const float2 hr = *reinterpret_cast<const float2*>(rela   + (size_t)rel * 64 + 2 * lane);

        float p0 = hs.x * wsa[0] + hs.y * wsb[0];
        float p1 = hs.x * wsa[1] + hs.y * wsb[1];
        float p2 = hs.x * wsa[2] + hs.y * wsb[2];
        float p3 = hs.x * wsa[3] + hs.y * wsb[3];
        float p4 = hs.x * wsa[4] + hs.y * wsb[4];
        #pragma unroll
        for (int off = 16; off > 0; off >>= 1) {
            p0 += __shfl_xor_sync(0xFFFFFFFFu, p0, off);
            p1 += __shfl_xor_sync(0xFFFFFFFFu, p1, off);
            p2 += __shfl_xor_sync(0xFFFFFFFFu, p2, off);
            p3 += __shfl_xor_sync(0xFFFFFFFFu, p3, off);
            p4 += __shfl_xor_sync(0xFFFFFFFFu, p4, off);
        }

        const float4 c4 = *reinterpret_cast<const float4*>(g_crel + rel * 8);
        const float  c5 = g_crel[rel * 8 + 4];
        const float4 q4 = *reinterpret_cast<const float4*>(g_cq + r_idx * 8);
        const float  q5 = g_cq[r_idx * 8 + 4];

        float z = walb;
        z += fmaxf(p0 + c4.x + q4.x, 0.f) * wal[0];
        z += fmaxf(p1 + c4.y + q4.y, 0.f) * wal[1];
        z += fmaxf(p2 + c4.z + q4.z, 0.f) * wal[2];
        z += fmaxf(p3 + c4.w + q4.w, 0.f) * wal[3];
        z += fmaxf(p4 + c5   + q5,   0.f) * wal[4];
        const float alpha = 1.f / (1.f + expf(-z));

        unsigned* ap = g_agg_enc + (size_t)obj * 64 + 2 * lane;
        atomicMax(ap,     encf(alpha * (hs.x - hr.x)));
        atomicMax(ap + 1, encf(alpha * (hs.y - hr.y)));
    }
}

// ---------------------------------------------------------------------------
// K3: node GEMM — node_msg = dec(agg)@M + Wnode_b; s0 = dec(agg)·v0; s1 = ·v1
//     Tile: 128 rows x 64 cols per block, 256 threads, 4x8 register tiles.
//     As: [128][65] (stride 65 -> conflict-free scalar reads)
//     Ms: [64][68]  (stride 68 -> float4-aligned col reads)
// ---------------------------------------------------------------------------
#define AS_STRIDE 65
#define MS_STRIDE 68
#define GEMM_SMEM ((128 * AS_STRIDE + 64 * MS_STRIDE) * 4)

__global__ void __launch_bounds__(256, 4)
k_gemm(int n_node, const float* __restrict__ Wnode_b)
{
    extern __shared__ float smem[];
    float* As = smem;                       // 128 * 65
    float* Ms = smem + 128 * AS_STRIDE;     // 64 * 68

    const int tid = threadIdx.x;
    for (int i = tid; i < 64 * 66; i += 256)
        Ms[(i / 66) * MS_STRIDE + (i % 66)] = g_Mext[i];

    const int rb = blockIdx.x * 128;
    const uint4* src = reinterpret_cast<const uint4*>(g_agg_enc + (size_t)rb * 64);
    const bool full = (rb + 128 <= n_node);

    #pragma unroll
    for (int t = 0; t < 8; t++) {
        int vidx = tid + t * 256;          // uint4 index 0..2047
        int r  = vidx >> 4;                // 16 uint4 per 64-wide row
        int k4 = (vidx & 15) * 4;
        uint4 u = make_uint4(ENC_NEGINF, ENC_NEGINF, ENC_NEGINF, ENC_NEGINF);
        if (full || rb + r < n_node) u = src[vidx];
        float* dst = As + r * AS_STRIDE + k4;
        dst[0] = dec0(u.x); dst[1] = dec0(u.y);
        dst[2] = dec0(u.z); dst[3] = dec0(u.w);
    }
    __syncthreads();

    const int tx = tid & 7;    // col group: 8 cols
    const int ty = tid >> 3;   // row group: 4 rows

    float acc[4][8];
    #pragma unroll
    for (int i = 0; i < 4; i++)
        #pragma unroll
        for (int c = 0; c < 8; c++) acc[i][c] = 0.f;

    const float* arow = As + ty * 4 * AS_STRIDE;
    const float* mcol = Ms + tx * 8;

    #pragma unroll 8
    for (int k = 0; k < 64; k++) {
        const float4 m0 = *reinterpret_cast<const float4*>(mcol + k * MS_STRIDE);
        const float4 m1 = *reinterpret_cast<const float4*>(mcol + k * MS_STRIDE + 4);
        #pragma unroll
        for (int i = 0; i < 4; i++) {
            const float a = arow[i * AS_STRIDE + k];
            acc[i][0] += a * m0.x; acc[i][1] += a * m0.y;
            acc[i][2] += a * m0.z; acc[i][3] += a * m0.w;
            acc[i][4] += a * m1.x; acc[i][5] += a * m1.y;
            acc[i][6] += a * m1.z; acc[i][7] += a * m1.w;
        }
    }

    const float4 b0 = *reinterpret_cast<const float4*>(Wnode_b + tx * 8);
    const float4 b1 = *reinterpret_cast<const float4*>(Wnode_b + tx * 8 + 4);
    #pragma unroll
    for (int i = 0; i < 4; i++) {
        int grow = rb + ty * 4 + i;
        if (grow < n_node) {
            float* op = g_node_msg + (size_t)grow * 64 + tx * 8;
            *reinterpret_cast<float4*>(op) =
                make_float4(acc[i][0] + b0.x, acc[i][1] + b0.y,
                            acc[i][2] + b0.z, acc[i][3] + b0.w);
            *reinterpret_cast<float4*>(op + 4) =
                make_float4(acc[i][4] + b1.x, acc[i][5] + b1.y,
                            acc[i][6] + b1.z, acc[i][7] + b1.w);
        }
    }

    // s0/s1 epilogue: rows 0..127, one per thread (threads 0..127)
    if (tid < 128) {
        int grow = rb + tid;
        if (grow < n_node) {
            float s0 = 0.f, s1 = 0.f;
            const float* ar = As + tid * AS_STRIDE;
            #pragma unroll 8
            for (int k = 0; k < 64; k++) {
                const float a = ar[k];
                s0 += a * Ms[k * MS_STRIDE + 64];
                s1 += a * Ms[k * MS_STRIDE + 65];
            }
            g_s0[grow] = s0;
            g_s1[grow] = s1;
        }
    }
}

// ---------------------------------------------------------------------------
// K4: edge scores + global max
// ---------------------------------------------------------------------------
__global__ void __launch_bounds__(256)
k_score(const int* __restrict__ edges, const float* __restrict__ attn_b, int n_edge)
{
    const int e = blockIdx.x * 256 + threadIdx.x;
    float sc = -FLT_MAX;
    if (e < n_edge) {
        int2 so = *reinterpret_cast<const int2*>(edges + (size_t)e * 6 + 4);
        float s = g_s0[so.x] + g_s1[so.y] + __ldg(attn_b);
        sc = (s > 0.f) ? s : 0.2f * s;
        g_scores[e] = sc;
    }
    __shared__ float red[8];
    const int lane = threadIdx.x & 31, wid = threadIdx.x >> 5;
    #pragma unroll
    for (int off = 16; off > 0; off >>= 1)
        sc = fmaxf(sc, __shfl_xor_sync(0xFFFFFFFFu, sc, off));
    if (lane == 0) red[wid] = sc;
    __syncthreads();
    if (wid == 0) {
        float v = (lane < 8) ? red[lane] : -FLT_MAX;
        #pragma unroll
        for (int off = 4; off > 0; off >>= 1)
            v = fmaxf(v, __shfl_xor_sync(0xFFFFFFFFu, v, off));
        if (lane == 0) atomicMax(&g_max_enc, encf(v));
    }
}

// ---------------------------------------------------------------------------
// K5: exp(score - max) in place + global sum
// ---------------------------------------------------------------------------
__global__ void __launch_bounds__(256)
k_expsum(int n_edge)
{
    const float gm = decf(g_max_enc);
    const int e = blockIdx.x * 256 + threadIdx.x;
    float v = 0.f;
    if (e < n_edge) {
        v = expf(g_scores[e] - gm);
        g_scores[e] = v;
    }
    __shared__ float red[8];
    const int lane = threadIdx.x & 31, wid = threadIdx.x >> 5;
    #pragma unroll
    for (int off = 16; off > 0; off >>= 1)
        v += __shfl_xor_sync(0xFFFFFFFFu, v, off);
    if (lane == 0) red[wid] = v;
    __syncthreads();
    if (wid == 0) {
        float s = (lane < 8) ? red[lane] : 0.f;
        #pragma unroll
        for (int off = 4; off > 0; off >>= 1)
            s += __shfl_xor_sync(0xFFFFFFFFu, s, off);
        if (lane == 0) atomicAdd(&g_sum, s);
    }
}

// ---------------------------------------------------------------------------
// K6: final weighted scatter — out[sub] += w_e * node_msg[obj]
//     16 threads per edge, vectorized red.global.add.v4.f32 (1 RED.128/lane)
// ---------------------------------------------------------------------------
__global__ void __launch_bounds__(256)
k_final(const int* __restrict__ edges, float* __restrict__ out, int n_edge)
{
    const float inv = 1.f / g_sum;
    const int t = blockIdx.x * 256 + threadIdx.x;
    const int e = t >> 4;
    const int q = t & 15;
    if (e >= n_edge) return;

    int2 so = *reinterpret_cast<const int2*>(edges + (size_t)e * 6 + 4);
    const float wgt = g_scores[e] * inv;
    const float4 m = *reinterpret_cast<const float4*>(
        g_node_msg + (size_t)so.y * 64 + q * 4);
    float* op = out + (size_t)so.x * 64 + q * 4;
    asm volatile("red.global.add.v4.f32 [%0], {%1, %2, %3, %4};"
                 :: "l"(op), "f"(wgt * m.x), "f"(wgt * m.y),
                    "f"(wgt * m.z), "f"(wgt * m.w)
                 : "memory");
}

// ---------------------------------------------------------------------------
// kernel_launch
// ---------------------------------------------------------------------------
extern "C" void kernel_launch(void* const* d_in, const int* in_sizes, int n_in,
                              void* d_out, int out_size)
{
    const float* hidden    = (const float*)d_in[0];
    const float* rela      = (const float*)d_in[1];
    const float* Ws        = (const float*)d_in[2];
    const float* Wr        = (const float*)d_in[3];
    const float* Wqr_w     = (const float*)d_in[4];
    const float* Wqr_b     = (const float*)d_in[5];
    const float* walpha_w  = (const float*)d_in[6];
    const float* walpha_b  = (const float*)d_in[7];
    const float* Wh        = (const float*)d_in[8];
    const float* attn_fc_w = (const float*)d_in[9];
    const float* attn_fc_b = (const float*)d_in[10];
    const float* Wnode_w   = (const float*)d_in[11];
    const float* Wnode_b   = (const float*)d_in[12];
    const int*   q_rel     = (const int*)d_in[14];
    const int*   edges     = (const int*)d_in[15];
    float*       out       = (float*)d_out;

    const int n_edge = in_sizes[15] / 6;
    const int n_node = in_sizes[16] / 2;
    const int nrel   = in_sizes[1] / 64;
    const int batch  = in_sizes[14];

    static bool attr_set = false;
    if (!attr_set) {
        cudaFuncSetAttribute(k_gemm, cudaFuncAttributeMaxDynamicSharedMemorySize,
                             GEMM_SMEM);
        attr_set = true;
    }

    // K0: precompute small tables
    k_setup<<<32, 256>>>(Wh, Wnode_w, attn_fc_w, rela, Wr, Wqr_w, Wqr_b,
                         q_rel, nrel, batch);

    // K1: init scratch + output
    k_init<<<4096, 256>>>(out, n_node * 64, out_size);

    // K2: edge messages + segment max
    k_edge1<<<2368, 256>>>(hidden, rela, Ws, walpha_w, walpha_b, edges, n_edge);

    // K3: fused node GEMM (node_msg, s0, s1)
    k_gemm<<<(n_node + 127) / 128, 256, GEMM_SMEM>>>(n_node, Wnode_b);

    // K4/K5: softmax statistics
    k_score<<<(n_edge + 255) / 256, 256>>>(edges, attn_fc_b, n_edge);
    k_expsum<<<(n_edge + 255) / 256, 256>>>(n_edge);

    // K6: weighted scatter to output (16 threads/edge, RED.128)
    k_final<<<(n_edge * 16 + 255) / 256, 256>>>(edges, out, n_edge);
}

// round 3
// speedup vs baseline: 1.1264x; 1.0084x over previous
#include <cuda_runtime.h>
#include <cfloat>
#include <cstdint>

// ---------------------------------------------------------------------------
// Problem-size constants
// ---------------------------------------------------------------------------
#define N_NODE_MAX 500000
#define N_EDGE_MAX 1000000
#define NREL_MAX   512
#define BATCH_MAX  64

#define ENC_NEGINF 0x007FFFFFu

// ---------------------------------------------------------------------------
// Device scratch
// ---------------------------------------------------------------------------
__device__ unsigned g_agg_enc[(size_t)N_NODE_MAX * 64];  // encoded segment-max
__device__ float    g_node_msg[(size_t)N_NODE_MAX * 64]; // agg@M + Wnode_b
__device__ float    g_s0[N_NODE_MAX];
__device__ float    g_s1[N_NODE_MAX];
__device__ float    g_scores[N_EDGE_MAX];
__device__ float    g_Mext[64 * 66];                      // [k][c]: c<64 -> M, 64->v0, 65->v1
__device__ float    g_crel[NREL_MAX * 8];                 // rela@Wr, padded stride 8
__device__ float    g_cq[BATCH_MAX * 8];                  // rela[q_rel]@Wqr + Wqr_b
__device__ unsigned g_max_enc;
__device__ float    g_sum;

// ---------------------------------------------------------------------------
// Order-preserving float <-> uint encoding (for atomicMax on floats)
// ---------------------------------------------------------------------------
__device__ __forceinline__ unsigned encf(float x) {
    unsigned u = __float_as_uint(x);
    return (u & 0x80000000u) ? ~u : (u | 0x80000000u);
}
__device__ __forceinline__ float decf(unsigned u) {
    return (u & 0x80000000u) ? __uint_as_float(u & 0x7FFFFFFFu)
                             : __uint_as_float(~u);
}
__device__ __forceinline__ float dec0(unsigned u) {   // decode, -inf -> 0
    return (u == ENC_NEGINF) ? 0.f : decf(u);
}

// ---------------------------------------------------------------------------
// Packed f32x2 helpers (Blackwell fma pipe executes 2 FMA lanes / instr)
// ---------------------------------------------------------------------------
__device__ __forceinline__ unsigned long long pack2(float a) {
    unsigned long long r;
    asm("mov.b64 %0, {%1, %1};" : "=l"(r) : "r"(__float_as_uint(a)));
    return r;
}
__device__ __forceinline__ void ffma2(unsigned long long& d,
                                      unsigned long long a,
                                      unsigned long long b) {
    asm("fma.rn.f32x2 %0, %1, %2, %0;" : "+l"(d) : "l"(a), "l"(b));
}
__device__ __forceinline__ float2 unpack2(unsigned long long v) {
    unsigned lo, hi;
    asm("mov.b64 {%0, %1}, %2;" : "=r"(lo), "=r"(hi) : "l"(v));
    return make_float2(__uint_as_float(lo), __uint_as_float(hi));
}

// ---------------------------------------------------------------------------
// K0: setup — precompute M_ext = [Wh@Wnode | Wh@w0 | Wh@w1], crel, cq
// ---------------------------------------------------------------------------
__global__ void k_setup(const float* __restrict__ Wh,
                        const float* __restrict__ Wnode,
                        const float* __restrict__ attn_w,   // (128,1)
                        const float* __restrict__ rela,
                        const float* __restrict__ Wr,
                        const float* __restrict__ Wqr_w,
                        const float* __restrict__ Wqr_b,
                        const int*   __restrict__ q_rel,
                        int nrel, int batch)
{
    int gtid   = blockIdx.x * blockDim.x + threadIdx.x;
    int stride = gridDim.x * blockDim.x;

    for (int i = gtid; i < 64 * 66; i += stride) {
        int k = i / 66, c = i % 66;
        float s = 0.f;
        if (c < 64) {
            #pragma unroll 8
            for (int j = 0; j < 64; j++) s += Wh[k * 64 + j] * Wnode[j * 64 + c];
        } else {
            const float* w = attn_w + (c - 64) * 64;
            #pragma unroll 8
            for (int j = 0; j < 64; j++) s += Wh[k * 64 + j] * w[j];
        }
        g_Mext[i] = s;
    }
    for (int i = gtid; i < nrel * 5; i += stride) {
        int r = i / 5, j = i % 5;
        float s = 0.f;
        #pragma unroll 8
        for (int k = 0; k < 64; k++) s += rela[r * 64 + k] * Wr[k * 5 + j];
        g_crel[r * 8 + j] = s;
    }
    for (int i = gtid; i < batch * 5; i += stride) {
        int b = i / 5, j = i % 5;
        int qr = q_rel[b];
        float s = Wqr_b[j];
        #pragma unroll 8
        for (int k = 0; k < 64; k++) s += rela[qr * 64 + k] * Wqr_w[k * 5 + j];
        g_cq[b * 8 + j] = s;
    }
}

// ---------------------------------------------------------------------------
// K1: init — agg_enc := enc(-inf), out := 0, global max/sum scalars
// ---------------------------------------------------------------------------
__global__ void k_init(float* __restrict__ out, int agg_elems, int out_elems)
{
    size_t i      = (size_t)blockIdx.x * blockDim.x + threadIdx.x;
    size_t stride = (size_t)gridDim.x * blockDim.x;

    uint4*  ap = reinterpret_cast<uint4*>(g_agg_enc);
    float4* op = reinterpret_cast<float4*>(out);
    size_t  na = (size_t)agg_elems >> 2;
    size_t  no = (size_t)out_elems >> 2;
    uint4   ev = make_uint4(ENC_NEGINF, ENC_NEGINF, ENC_NEGINF, ENC_NEGINF);
    float4  zv = make_float4(0.f, 0.f, 0.f, 0.f);

    for (size_t t = i; t < na; t += stride) ap[t] = ev;
    for (size_t t = i; t < no; t += stride) op[t] = zv;
    if (i == 0) { g_max_enc = 0u; g_sum = 0.f; }
}

// ---------------------------------------------------------------------------
// K2: edge pass 1 — alpha-weighted message + segment-max (warp per edge)
// ---------------------------------------------------------------------------
__global__ void __launch_bounds__(256)
k_edge1(const float* __restrict__ hidden,
        const float* __restrict__ rela,
        const float* __restrict__ Ws,       // (64,5)
        const float* __restrict__ wa,       // (5,1)
        const float* __restrict__ wab,      // (1,)
        const int*   __restrict__ edges,
        int n_edge)
{
    const int lane = threadIdx.x & 31;

    float wsa[5], wsb[5], wal[5];
    #pragma unroll
    for (int j = 0; j < 5; j++) {
        wsa[j] = __ldg(Ws + (2 * lane) * 5 + j);
        wsb[j] = __ldg(Ws + (2 * lane + 1) * 5 + j);
        wal[j] = __ldg(wa + j);
    }
    const float walb = __ldg(wab);

    const int warps_total = gridDim.x * (blockDim.x >> 5);
    int w = blockIdx.x * (blockDim.x >> 5) + (threadIdx.x >> 5);

    for (int e = w; e < n_edge; e += warps_total) {
        const int* ep = edges + (size_t)e * 6;
        int2 i01 = *reinterpret_cast<const int2*>(ep);       // r_idx, _
        int2 i23 = *reinterpret_cast<const int2*>(ep + 2);   // rel, _
        int2 i45 = *reinterpret_cast<const int2*>(ep + 4);   // sub, obj
        const int r_idx = i01.x, rel = i23.x, sub = i45.x, obj = i45.y;

        const float2 hs = *reinterpret_cast<const float2*>(hidden + (size_t)sub * 64 + 2 * lane);
        const float2 hr = *reinterpret_cast<const float2*>(rela   + (size_t)rel * 64 + 2 * lane);

        float p0 = hs.x * wsa[0] + hs.y * wsb[0];
        float p1 = hs.x * wsa[1] + hs.y * wsb[1];
        float p2 = hs.x * wsa[2] + hs.y * wsb[2];
        float p3 = hs.x * wsa[3] + hs.y * wsb[3];
        float p4 = hs.x * wsa[4] + hs.y * wsb[4];
        #pragma unroll
        for (int off = 16; off > 0; off >>= 1) {
            p0 += __shfl_xor_sync(0xFFFFFFFFu, p0, off);
            p1 += __shfl_xor_sync(0xFFFFFFFFu, p1, off);
            p2 += __shfl_xor_sync(0xFFFFFFFFu, p2, off);
            p3 += __shfl_xor_sync(0xFFFFFFFFu, p3, off);
            p4 += __shfl_xor_sync(0xFFFFFFFFu, p4, off);
        }

        const float4 c4 = *reinterpret_cast<const float4*>(g_crel + rel * 8);
        const float  c5 = g_crel[rel * 8 + 4];
        const float4 q4 = *reinterpret_cast<const float4*>(g_cq + r_idx * 8);
        const float  q5 = g_cq[r_idx * 8 + 4];

        float z = walb;
        z += fmaxf(p0 + c4.x + q4.x, 0.f) * wal[0];
        z += fmaxf(p1 + c4.y + q4.y, 0.f) * wal[1];
        z += fmaxf(p2 + c4.z + q4.z, 0.f) * wal[2];
        z += fmaxf(p3 + c4.w + q4.w, 0.f) * wal[3];
        z += fmaxf(p4 + c5   + q5,   0.f) * wal[4];
        const float alpha = 1.f / (1.f + expf(-z));

        unsigned* ap = g_agg_enc + (size_t)obj * 64 + 2 * lane;
        atomicMax(ap,     encf(alpha * (hs.x - hr.x)));
        atomicMax(ap + 1, encf(alpha * (hs.y - hr.y)));
    }
}

// ---------------------------------------------------------------------------
// K3: node GEMM — node_msg = dec(agg)@M + Wnode_b; s0 = dec(agg)·v0; s1 = ·v1
//     Tile: 128 rows x 64 cols per block, 256 threads, 4 rows x 4 f32x2-pairs
//     per thread. Inner loop uses packed fma.rn.f32x2 (2 FMA lanes / instr).
// ---------------------------------------------------------------------------
#define AS_STRIDE 65
#define MS_STRIDE 68
#define GEMM_SMEM ((128 * AS_STRIDE + 64 * MS_STRIDE) * 4)

__global__ void __launch_bounds__(256, 4)
k_gemm(int n_node, const float* __restrict__ Wnode_b)
{
    extern __shared__ float smem[];
    float* As = smem;                       // 128 * 65
    float* Ms = smem + 128 * AS_STRIDE;     // 64 * 68

    const int tid = threadIdx.x;
    for (int i = tid; i < 64 * 66; i += 256)
        Ms[(i / 66) * MS_STRIDE + (i % 66)] = g_Mext[i];

    const int rb = blockIdx.x * 128;
    const uint4* src = reinterpret_cast<const uint4*>(g_agg_enc + (size_t)rb * 64);
    const bool full = (rb + 128 <= n_node);

    #pragma unroll
    for (int t = 0; t < 8; t++) {
        int vidx = tid + t * 256;          // uint4 index 0..2047
        int r  = vidx >> 4;                // 16 uint4 per 64-wide row
        int k4 = (vidx & 15) * 4;
        uint4 u = make_uint4(ENC_NEGINF, ENC_NEGINF, ENC_NEGINF, ENC_NEGINF);
        if (full || rb + r < n_node) u = src[vidx];
        float* dst = As + r * AS_STRIDE + k4;
        dst[0] = dec0(u.x); dst[1] = dec0(u.y);
        dst[2] = dec0(u.z); dst[3] = dec0(u.w);
    }
    __syncthreads();

    const int tx = tid & 7;    // col group: 8 cols = 4 f32x2 pairs
    const int ty = tid >> 3;   // row group: 4 rows

    unsigned long long acc[4][4];
    #pragma unroll
    for (int i = 0; i < 4; i++)
        #pragma unroll
        for (int c = 0; c < 4; c++) acc[i][c] = 0ull;

    const float* arow = As + ty * 4 * AS_STRIDE;
    const float* mcol = Ms + tx * 8;

    #pragma unroll 4
    for (int k = 0; k < 64; k++) {
        // 8 m-values = 4 packed pairs, two LDS.128
        const ulonglong2 mp0 = *reinterpret_cast<const ulonglong2*>(mcol + k * MS_STRIDE);
        const ulonglong2 mp1 = *reinterpret_cast<const ulonglong2*>(mcol + k * MS_STRIDE + 4);
        #pragma unroll
        for (int i = 0; i < 4; i++) {
            const unsigned long long aa = pack2(arow[i * AS_STRIDE + k]);
            ffma2(acc[i][0], aa, mp0.x);
            ffma2(acc[i][1], aa, mp0.y);
            ffma2(acc[i][2], aa, mp1.x);
            ffma2(acc[i][3], aa, mp1.y);
        }
    }

    const float4 b0 = *reinterpret_cast<const float4*>(Wnode_b + tx * 8);
    const float4 b1 = *reinterpret_cast<const float4*>(Wnode_b + tx * 8 + 4);
    #pragma unroll
    for (int i = 0; i < 4; i++) {
        int grow = rb + ty * 4 + i;
        if (grow < n_node) {
            float2 a0 = unpack2(acc[i][0]);
            float2 a1 = unpack2(acc[i][1]);
            float2 a2 = unpack2(acc[i][2]);
            float2 a3 = unpack2(acc[i][3]);
            float* op = g_node_msg + (size_t)grow * 64 + tx * 8;
            *reinterpret_cast<float4*>(op) =
                make_float4(a0.x + b0.x, a0.y + b0.y, a1.x + b0.z, a1.y + b0.w);
            *reinterpret_cast<float4*>(op + 4) =
                make_float4(a2.x + b1.x, a2.y + b1.y, a3.x + b1.z, a3.y + b1.w);
        }
    }

    // s0/s1 epilogue: rows 0..127, one per thread — packed (s0,s1) pair;
    // v0[k],v1[k] are adjacent at Ms[k][64..65] -> single ld.shared.b64
    if (tid < 128) {
        int grow = rb + tid;
        if (grow < n_node) {
            unsigned long long s01 = 0ull;
            const float* ar = As + tid * AS_STRIDE;
            #pragma unroll 8
            for (int k = 0; k < 64; k++) {
                const unsigned long long v01 =
                    *reinterpret_cast<const unsigned long long*>(Ms + k * MS_STRIDE + 64);
                ffma2(s01, pack2(ar[k]), v01);
            }
            float2 s = unpack2(s01);
            g_s0[grow] = s.x;
            g_s1[grow] = s.y;
        }
    }
}

// ---------------------------------------------------------------------------
// K4: edge scores + global max
// ---------------------------------------------------------------------------
__global__ void __launch_bounds__(256)
k_score(const int* __restrict__ edges, const float* __restrict__ attn_b, int n_edge)
{
    const int e = blockIdx.x * 256 + threadIdx.x;
    float sc = -FLT_MAX;
    if (e < n_edge) {
        int2 so = *reinterpret_cast<const int2*>(edges + (size_t)e * 6 + 4);
        float s = g_s0[so.x] + g_s1[so.y] + __ldg(attn_b);
        sc = (s > 0.f) ? s : 0.2f * s;
        g_scores[e] = sc;
    }
    __shared__ float red[8];
    const int lane = threadIdx.x & 31, wid = threadIdx.x >> 5;
    #pragma unroll
    for (int off = 16; off > 0; off >>= 1)
        sc = fmaxf(sc, __shfl_xor_sync(0xFFFFFFFFu, sc, off));
    if (lane == 0) red[wid] = sc;
    __syncthreads();
    if (wid == 0) {
        float v = (lane < 8) ? red[lane] : -FLT_MAX;
        #pragma unroll
        for (int off = 4; off > 0; off >>= 1)
            v = fmaxf(v, __shfl_xor_sync(0xFFFFFFFFu, v, off));
        if (lane == 0) atomicMax(&g_max_enc, encf(v));
    }
}

// ---------------------------------------------------------------------------
// K5: exp(score - max) in place + global sum
// ---------------------------------------------------------------------------
__global__ void __launch_bounds__(256)
k_expsum(int n_edge)
{
    const float gm = decf(g_max_enc);
    const int e = blockIdx.x * 256 + threadIdx.x;
    float v = 0.f;
    if (e < n_edge) {
        v = expf(g_scores[e] - gm);
        g_scores[e] = v;
    }
    __shared__ float red[8];
    const int lane = threadIdx.x & 31, wid = threadIdx.x >> 5;
    #pragma unroll
    for (int off = 16; off > 0; off >>= 1)
        v += __shfl_xor_sync(0xFFFFFFFFu, v, off);
    if (lane == 0) red[wid] = v;
    __syncthreads();
    if (wid == 0) {
        float s = (lane < 8) ? red[lane] : 0.f;
        #pragma unroll
        for (int off = 4; off > 0; off >>= 1)
            s += __shfl_xor_sync(0xFFFFFFFFu, s, off);
        if (lane == 0) atomicAdd(&g_sum, s);
    }
}

// ---------------------------------------------------------------------------
// K6: final weighted scatter — out[sub] += w_e * node_msg[obj]
//     16 threads per edge, vectorized red.global.add.v4.f32 (1 RED.128/lane)
// ---------------------------------------------------------------------------
__global__ void __launch_bounds__(256)
k_final(const int* __restrict__ edges, float* __restrict__ out, int n_edge)
{
    const float inv = 1.f / g_sum;
    const int t = blockIdx.x * 256 + threadIdx.x;
    const int e = t >> 4;
    const int q = t & 15;
    if (e >= n_edge) return;

    int2 so = *reinterpret_cast<const int2*>(edges + (size_t)e * 6 + 4);
    const float wgt = g_scores[e] * inv;
    const float4 m = *reinterpret_cast<const float4*>(
        g_node_msg + (size_t)so.y * 64 + q * 4);
    float* op = out + (size_t)so.x * 64 + q * 4;
    asm volatile("red.global.add.v4.f32 [%0], {%1, %2, %3, %4};"
                 :: "l"(op), "f"(wgt * m.x), "f"(wgt * m.y),
                    "f"(wgt * m.z), "f"(wgt * m.w)
                 : "memory");
}

// ---------------------------------------------------------------------------
// kernel_launch
// ---------------------------------------------------------------------------
extern "C" void kernel_launch(void* const* d_in, const int* in_sizes, int n_in,
                              void* d_out, int out_size)
{
    const float* hidden    = (const float*)d_in[0];
    const float* rela      = (const float*)d_in[1];
    const float* Ws        = (const float*)d_in[2];
    const float* Wr        = (const float*)d_in[3];
    const float* Wqr_w     = (const float*)d_in[4];
    const float* Wqr_b     = (const float*)d_in[5];
    const float* walpha_w  = (const float*)d_in[6];
    const float* walpha_b  = (const float*)d_in[7];
    const float* Wh        = (const float*)d_in[8];
    const float* attn_fc_w = (const float*)d_in[9];
    const float* attn_fc_b = (const float*)d_in[10];
    const float* Wnode_w   = (const float*)d_in[11];
    const float* Wnode_b   = (const float*)d_in[12];
    const int*   q_rel     = (const int*)d_in[14];
    const int*   edges     = (const int*)d_in[15];
    float*       out       = (float*)d_out;

    const int n_edge = in_sizes[15] / 6;
    const int n_node = in_sizes[16] / 2;
    const int nrel   = in_sizes[1] / 64;
    const int batch  = in_sizes[14];

    static bool attr_set = false;
    if (!attr_set) {
        cudaFuncSetAttribute(k_gemm, cudaFuncAttributeMaxDynamicSharedMemorySize,
                             GEMM_SMEM);
        attr_set = true;
    }

    // K0: precompute small tables
    k_setup<<<32, 256>>>(Wh, Wnode_w, attn_fc_w, rela, Wr, Wqr_w, Wqr_b,
                         q_rel, nrel, batch);

    // K1: init scratch + output
    k_init<<<4096, 256>>>(out, n_node * 64, out_size);

    // K2: edge messages + segment max
    k_edge1<<<2368, 256>>>(hidden, rela, Ws, walpha_w, walpha_b, edges, n_edge);

    // K3: fused node GEMM (node_msg, s0, s1) — packed f32x2 inner loop
    k_gemm<<<(n_node + 127) / 128, 256, GEMM_SMEM>>>(n_node, Wnode_b);

    // K4/K5: softmax statistics
    k_score<<<(n_edge + 255) / 256, 256>>>(edges, attn_fc_b, n_edge);
    k_expsum<<<(n_edge + 255) / 256, 256>>>(n_edge);

    // K6: weighted scatter to output (16 threads/edge, RED.128)
    k_final<<<(n_edge * 16 + 255) / 256, 256>>>(edges, out, n_edge);
}

// round 4
// speedup vs baseline: 1.1846x; 1.0517x over previous
#include <cuda_runtime.h>
#include <cfloat>
#include <cstdint>

// ---------------------------------------------------------------------------
// Problem-size constants
// ---------------------------------------------------------------------------
#define N_NODE_MAX 500000
#define N_EDGE_MAX 1000000
#define NREL_MAX   512
#define BATCH_MAX  64

#define ENC_NEGINF 0x007FFFFFu

// ---------------------------------------------------------------------------
// Device scratch
// ---------------------------------------------------------------------------
__device__ unsigned g_agg_enc[(size_t)N_NODE_MAX * 64];  // encoded segment-max
__device__ float    g_node_msg[(size_t)N_NODE_MAX * 64]; // agg@M + Wnode_b
__device__ float    g_s0[N_NODE_MAX];
__device__ float    g_s1[N_NODE_MAX];
__device__ float    g_scores[N_EDGE_MAX];
__device__ float    g_Mext[64 * 66];                      // [k][c]: c<64 -> M, 64->v0, 65->v1
__device__ float    g_crel[NREL_MAX * 8];                 // rela@Wr, padded stride 8
__device__ float    g_cq[BATCH_MAX * 8];                  // rela[q_rel]@Wqr + Wqr_b
__device__ unsigned g_max_enc;
__device__ float    g_sum;

// ---------------------------------------------------------------------------
// Order-preserving float <-> uint encoding (for atomicMax on floats)
// ---------------------------------------------------------------------------
__device__ __forceinline__ unsigned encf(float x) {
    unsigned u = __float_as_uint(x);
    return (u & 0x80000000u) ? ~u : (u | 0x80000000u);
}
__device__ __forceinline__ float decf(unsigned u) {
    return (u & 0x80000000u) ? __uint_as_float(u & 0x7FFFFFFFu)
                             : __uint_as_float(~u);
}
__device__ __forceinline__ float dec0(unsigned u) {   // decode, -inf -> 0
    return (u == ENC_NEGINF) ? 0.f : decf(u);
}

// ---------------------------------------------------------------------------
// Packed f32x2 helpers
// ---------------------------------------------------------------------------
__device__ __forceinline__ unsigned long long pack2(float a) {
    unsigned long long r;
    asm("mov.b64 %0, {%1, %1};" : "=l"(r) : "r"(__float_as_uint(a)));
    return r;
}
__device__ __forceinline__ void ffma2(unsigned long long& d,
                                      unsigned long long a,
                                      unsigned long long b) {
    asm("fma.rn.f32x2 %0, %1, %2, %0;" : "+l"(d) : "l"(a), "l"(b));
}
__device__ __forceinline__ float2 unpack2(unsigned long long v) {
    unsigned lo, hi;
    asm("mov.b64 {%0, %1}, %2;" : "=r"(lo), "=r"(hi) : "l"(v));
    return make_float2(__uint_as_float(lo), __uint_as_float(hi));
}

// ---------------------------------------------------------------------------
// K0: setup — precompute M_ext = [Wh@Wnode | Wh@w0 | Wh@w1], crel, cq
// ---------------------------------------------------------------------------
__global__ void k_setup(const float* __restrict__ Wh,
                        const float* __restrict__ Wnode,
                        const float* __restrict__ attn_w,   // (128,1)
                        const float* __restrict__ rela,
                        const float* __restrict__ Wr,
                        const float* __restrict__ Wqr_w,
                        const float* __restrict__ Wqr_b,
                        const int*   __restrict__ q_rel,
                        int nrel, int batch)
{
    int gtid   = blockIdx.x * blockDim.x + threadIdx.x;
    int stride = gridDim.x * blockDim.x;

    for (int i = gtid; i < 64 * 66; i += stride) {
        int k = i / 66, c = i % 66;
        float s = 0.f;
        if (c < 64) {
            #pragma unroll 8
            for (int j = 0; j < 64; j++) s += Wh[k * 64 + j] * Wnode[j * 64 + c];
        } else {
            const float* w = attn_w + (c - 64) * 64;
            #pragma unroll 8
            for (int j = 0; j < 64; j++) s += Wh[k * 64 + j] * w[j];
        }
        g_Mext[i] = s;
    }
    for (int i = gtid; i < nrel * 5; i += stride) {
        int r = i / 5, j = i % 5;
        float s = 0.f;
        #pragma unroll 8
        for (int k = 0; k < 64; k++) s += rela[r * 64 + k] * Wr[k * 5 + j];
        g_crel[r * 8 + j] = s;
    }
    for (int i = gtid; i < batch * 5; i += stride) {
        int b = i / 5, j = i % 5;
        int qr = q_rel[b];
        float s = Wqr_b[j];
        #pragma unroll 8
        for (int k = 0; k < 64; k++) s += rela[qr * 64 + k] * Wqr_w[k * 5 + j];
        g_cq[b * 8 + j] = s;
    }
}

// ---------------------------------------------------------------------------
// K1: init — agg_enc := enc(-inf), out := 0, global max/sum scalars
// ---------------------------------------------------------------------------
__global__ void k_init(float* __restrict__ out, int agg_elems, int out_elems)
{
    size_t i      = (size_t)blockIdx.x * blockDim.x + threadIdx.x;
    size_t stride = (size_t)gridDim.x * blockDim.x;

    uint4*  ap = reinterpret_cast<uint4*>(g_agg_enc);
    float4* op = reinterpret_cast<float4*>(out);
    size_t  na = (size_t)agg_elems >> 2;
    size_t  no = (size_t)out_elems >> 2;
    uint4   ev = make_uint4(ENC_NEGINF, ENC_NEGINF, ENC_NEGINF, ENC_NEGINF);
    float4  zv = make_float4(0.f, 0.f, 0.f, 0.f);

    for (size_t t = i; t < na; t += stride) ap[t] = ev;
    for (size_t t = i; t < no; t += stride) op[t] = zv;
    if (i == 0) { g_max_enc = 0u; g_sum = 0.f; }
}

// ---------------------------------------------------------------------------
// K2: edge pass 1 — alpha-weighted message + segment-max (warp per edge)
// ---------------------------------------------------------------------------
__global__ void __launch_bounds__(256)
k_edge1(const float* __restrict__ hidden,
        const float* __restrict__ rela,
        const float* __restrict__ Ws,       // (64,5)
        const float* __restrict__ wa,       // (5,1)
        const float* __restrict__ wab,      // (1,)
        const int*   __restrict__ edges,
        int n_edge)
{
    const int lane = threadIdx.x & 31;

    float wsa[5], wsb[5], wal[5];
    #pragma unroll
    for (int j = 0; j < 5; j++) {
        wsa[j] = __ldg(Ws + (2 * lane) * 5 + j);
        wsb[j] = __ldg(Ws + (2 * lane + 1) * 5 + j);
        wal[j] = __ldg(wa + j);
    }
    const float walb = __ldg(wab);

    const int warps_total = gridDim.x * (blockDim.x >> 5);
    int w = blockIdx.x * (blockDim.x >> 5) + (threadIdx.x >> 5);

    for (int e = w; e < n_edge; e += warps_total) {
        const int* ep = edges + (size_t)e * 6;
        int2 i01 = *reinterpret_cast<const int2*>(ep);       // r_idx, _
        int2 i23 = *reinterpret_cast<const int2*>(ep + 2);   // rel, _
        int2 i45 = *reinterpret_cast<const int2*>(ep + 4);   // sub, obj
        const int r_idx = i01.x, rel = i23.x, sub = i45.x, obj = i45.y;

        const float2 hs = *reinterpret_cast<const float2*>(hidden + (size_t)sub * 64 + 2 * lane);
        const float2 hr = *reinterpret_cast<const float2*>(rela   + (size_t)rel * 64 + 2 * lane);

        float p0 = hs.x * wsa[0] + hs.y * wsb[0];
        float p1 = hs.x * wsa[1] + hs.y * wsb[1];
        float p2 = hs.x * wsa[2] + hs.y * wsb[2];
        float p3 = hs.x * wsa[3] + hs.y * wsb[3];
        float p4 = hs.x * wsa[4] + hs.y * wsb[4];
        #pragma unroll
        for (int off = 16; off > 0; off >>= 1) {
            p0 += __shfl_xor_sync(0xFFFFFFFFu, p0, off);
            p1 += __shfl_xor_sync(0xFFFFFFFFu, p1, off);
            p2 += __shfl_xor_sync(0xFFFFFFFFu, p2, off);
            p3 += __shfl_xor_sync(0xFFFFFFFFu, p3, off);
            p4 += __shfl_xor_sync(0xFFFFFFFFu, p4, off);
        }

        const float4 c4 = *reinterpret_cast<const float4*>(g_crel + rel * 8);
        const float  c5 = g_crel[rel * 8 + 4];
        const float4 q4 = *reinterpret_cast<const float4*>(g_cq + r_idx * 8);
        const float  q5 = g_cq[r_idx * 8 + 4];

        float z = walb;
        z += fmaxf(p0 + c4.x + q4.x, 0.f) * wal[0];
        z += fmaxf(p1 + c4.y + q4.y, 0.f) * wal[1];
        z += fmaxf(p2 + c4.z + q4.z, 0.f) * wal[2];
        z += fmaxf(p3 + c4.w + q4.w, 0.f) * wal[3];
        z += fmaxf(p4 + c5   + q5,   0.f) * wal[4];
        const float alpha = 1.f / (1.f + expf(-z));

        unsigned* ap = g_agg_enc + (size_t)obj * 64 + 2 * lane;
        atomicMax(ap,     encf(alpha * (hs.x - hr.x)));
        atomicMax(ap + 1, encf(alpha * (hs.y - hr.y)));
    }
}

// ---------------------------------------------------------------------------
// K3: node GEMM — node_msg = dec(agg)@M + Wnode_b; s0 = dec(agg)·v0; s1 = ·v1
//     Tile: 128 rows x 64 cols per block, 256 threads.
//     A vectorized over k (LDS.128, conflict-free broadcast).
//     M re-laid out as [k][half][tx][4] -> both LDS.128 conflict-free.
// ---------------------------------------------------------------------------
#define AS_STRIDE 68
#define GEMM_SMEM ((128 * AS_STRIDE + 64 * 64 + 128) * 4)

__global__ void __launch_bounds__(256, 4)
k_gemm(int n_node, const float* __restrict__ Wnode_b)
{
    extern __shared__ float smem[];
    float* As  = smem;                        // 128 * 68
    float* MsL = smem + 128 * AS_STRIDE;      // 64 * 64, [k][half][tx][4]
    float* Vs  = MsL + 64 * 64;               // 64 * 2, [k][{v0,v1}]

    const int tid = threadIdx.x;
    for (int i = tid; i < 64 * 66; i += 256) {
        int k = i / 66, c = i % 66;
        float v = g_Mext[i];
        if (c < 64)
            MsL[k * 64 + ((c & 4) ? 32 : 0) + (c >> 3) * 4 + (c & 3)] = v;
        else
            Vs[k * 2 + (c - 64)] = v;
    }

    const int rb = blockIdx.x * 128;
    const uint4* src = reinterpret_cast<const uint4*>(g_agg_enc + (size_t)rb * 64);
    const bool full = (rb + 128 <= n_node);

    #pragma unroll
    for (int t = 0; t < 8; t++) {
        int vidx = tid + t * 256;          // uint4 index 0..2047
        int r  = vidx >> 4;                // 16 uint4 per 64-wide row
        int k4 = (vidx & 15) * 4;
        uint4 u = make_uint4(ENC_NEGINF, ENC_NEGINF, ENC_NEGINF, ENC_NEGINF);
        if (full || rb + r < n_node) u = src[vidx];
        float* dst = As + r * AS_STRIDE + k4;
        dst[0] = dec0(u.x); dst[1] = dec0(u.y);
        dst[2] = dec0(u.z); dst[3] = dec0(u.w);
    }
    __syncthreads();

    const int tx = tid & 7;    // col group: 8 cols = 4 f32x2 pairs
    const int ty = tid >> 3;   // row group: 4 rows

    unsigned long long acc[4][4];
    #pragma unroll
    for (int i = 0; i < 4; i++)
        #pragma unroll
        for (int c = 0; c < 4; c++) acc[i][c] = 0ull;

    const float* arow  = As + ty * 4 * AS_STRIDE;
    const float* mbase = MsL + tx * 4;

    #pragma unroll 2
    for (int k4 = 0; k4 < 64; k4 += 4) {
        float4 a[4];
        #pragma unroll
        for (int i = 0; i < 4; i++)
            a[i] = *reinterpret_cast<const float4*>(arow + i * AS_STRIDE + k4);

        #pragma unroll
        for (int kk = 0; kk < 4; kk++) {
            const ulonglong2 mp0 = *reinterpret_cast<const ulonglong2*>(mbase + (k4 + kk) * 64);
            const ulonglong2 mp1 = *reinterpret_cast<const ulonglong2*>(mbase + (k4 + kk) * 64 + 32);
            #pragma unroll
            for (int i = 0; i < 4; i++) {
                const float av = (kk == 0) ? a[i].x : (kk == 1) ? a[i].y
                               : (kk == 2) ? a[i].z : a[i].w;
                const unsigned long long aa = pack2(av);
                ffma2(acc[i][0], aa, mp0.x);
                ffma2(acc[i][1], aa, mp0.y);
                ffma2(acc[i][2], aa, mp1.x);
                ffma2(acc[i][3], aa, mp1.y);
            }
        }
    }

    const float4 b0 = *reinterpret_cast<const float4*>(Wnode_b + tx * 8);
    const float4 b1 = *reinterpret_cast<const float4*>(Wnode_b + tx * 8 + 4);
    #pragma unroll
    for (int i = 0; i < 4; i++) {
        int grow = rb + ty * 4 + i;
        if (grow < n_node) {
            float2 a0 = unpack2(acc[i][0]);
            float2 a1 = unpack2(acc[i][1]);
            float2 a2 = unpack2(acc[i][2]);
            float2 a3 = unpack2(acc[i][3]);
            float* op = g_node_msg + (size_t)grow * 64 + tx * 8;
            *reinterpret_cast<float4*>(op) =
                make_float4(a0.x + b0.x, a0.y + b0.y, a1.x + b0.z, a1.y + b0.w);
            *reinterpret_cast<float4*>(op + 4) =
                make_float4(a2.x + b1.x, a2.y + b1.y, a3.x + b1.z, a3.y + b1.w);
        }
    }

    // s0/s1 epilogue: rows 0..127, one per thread — packed (s0,s1) pair;
    // Vs[k] is a broadcast ld.shared.b64
    if (tid < 128) {
        int grow = rb + tid;
        if (grow < n_node) {
            unsigned long long s01 = 0ull;
            const float* ar = As + tid * AS_STRIDE;
            #pragma unroll 8
            for (int k = 0; k < 64; k++) {
                const unsigned long long v01 =
                    *reinterpret_cast<const unsigned long long*>(Vs + k * 2);
                ffma2(s01, pack2(ar[k]), v01);
            }
            float2 s = unpack2(s01);
            g_s0[grow] = s.x;
            g_s1[grow] = s.y;
        }
    }
}

// ---------------------------------------------------------------------------
// K4: edge scores + global max
// ---------------------------------------------------------------------------
__global__ void __launch_bounds__(256)
k_score(const int* __restrict__ edges, const float* __restrict__ attn_b, int n_edge)
{
    const int e = blockIdx.x * 256 + threadIdx.x;
    float sc = -FLT_MAX;
    if (e < n_edge) {
        int2 so = *reinterpret_cast<const int2*>(edges + (size_t)e * 6 + 4);
        float s = g_s0[so.x] + g_s1[so.y] + __ldg(attn_b);
        sc = (s > 0.f) ? s : 0.2f * s;
        g_scores[e] = sc;
    }
    __shared__ float red[8];
    const int lane = threadIdx.x & 31, wid = threadIdx.x >> 5;
    #pragma unroll
    for (int off = 16; off > 0; off >>= 1)
        sc = fmaxf(sc, __shfl_xor_sync(0xFFFFFFFFu, sc, off));
    if (lane == 0) red[wid] = sc;
    __syncthreads();
    if (wid == 0) {
        float v = (lane < 8) ? red[lane] : -FLT_MAX;
        #pragma unroll
        for (int off = 4; off > 0; off >>= 1)
            v = fmaxf(v, __shfl_xor_sync(0xFFFFFFFFu, v, off));
        if (lane == 0) atomicMax(&g_max_enc, encf(v));
    }
}

// ---------------------------------------------------------------------------
// K5: exp(score - max) in place + global sum
// ---------------------------------------------------------------------------
__global__ void __launch_bounds__(256)
k_expsum(int n_edge)
{
    const float gm = decf(g_max_enc);
    const int e = blockIdx.x * 256 + threadIdx.x;
    float v = 0.f;
    if (e < n_edge) {
        v = expf(g_scores[e] - gm);
        g_scores[e] = v;
    }
    __shared__ float red[8];
    const int lane = threadIdx.x & 31, wid = threadIdx.x >> 5;
    #pragma unroll
    for (int off = 16; off > 0; off >>= 1)
        v += __shfl_xor_sync(0xFFFFFFFFu, v, off);
    if (lane == 0) red[wid] = v;
    __syncthreads();
    if (wid == 0) {
        float s = (lane < 8) ? red[lane] : 0.f;
        #pragma unroll
        for (int off = 4; off > 0; off >>= 1)
            s += __shfl_xor_sync(0xFFFFFFFFu, s, off);
        if (lane == 0) atomicAdd(&g_sum, s);
    }
}

// ---------------------------------------------------------------------------
// K6: final weighted scatter — out[sub] += w_e * node_msg[obj]
//     16 threads per edge, vectorized red.global.add.v4.f32 (1 RED.128/lane)
// ---------------------------------------------------------------------------
__global__ void __launch_bounds__(256)
k_final(const int* __restrict__ edges, float* __restrict__ out, int n_edge)
{
    const float inv = 1.f / g_sum;
    const int t = blockIdx.x * 256 + threadIdx.x;
    const int e = t >> 4;
    const int q = t & 15;
    if (e >= n_edge) return;

    int2 so = *reinterpret_cast<const int2*>(edges + (size_t)e * 6 + 4);
    const float wgt = g_scores[e] * inv;
    const float4 m = *reinterpret_cast<const float4*>(
        g_node_msg + (size_t)so.y * 64 + q * 4);
    float* op = out + (size_t)so.x * 64 + q * 4;
    asm volatile("red.global.add.v4.f32 [%0], {%1, %2, %3, %4};"
                 :: "l"(op), "f"(wgt * m.x), "f"(wgt * m.y),
                    "f"(wgt * m.z), "f"(wgt * m.w)
                 : "memory");
}

// ---------------------------------------------------------------------------
// kernel_launch
// ---------------------------------------------------------------------------
extern "C" void kernel_launch(void* const* d_in, const int* in_sizes, int n_in,
                              void* d_out, int out_size)
{
    const float* hidden    = (const float*)d_in[0];
    const float* rela      = (const float*)d_in[1];
    const float* Ws        = (const float*)d_in[2];
    const float* Wr        = (const float*)d_in[3];
    const float* Wqr_w     = (const float*)d_in[4];
    const float* Wqr_b     = (const float*)d_in[5];
    const float* walpha_w  = (const float*)d_in[6];
    const float* walpha_b  = (const float*)d_in[7];
    const float* Wh        = (const float*)d_in[8];
    const float* attn_fc_w = (const float*)d_in[9];
    const float* attn_fc_b = (const float*)d_in[10];
    const float* Wnode_w   = (const float*)d_in[11];
    const float* Wnode_b   = (const float*)d_in[12];
    const int*   q_rel     = (const int*)d_in[14];
    const int*   edges     = (const int*)d_in[15];
    float*       out       = (float*)d_out;

    const int n_edge = in_sizes[15] / 6;
    const int n_node = in_sizes[16] / 2;
    const int nrel   = in_sizes[1] / 64;
    const int batch  = in_sizes[14];

    static bool attr_set = false;
    if (!attr_set) {
        cudaFuncSetAttribute(k_gemm, cudaFuncAttributeMaxDynamicSharedMemorySize,
                             GEMM_SMEM);
        attr_set = true;
    }

    // K0: precompute small tables
    k_setup<<<32, 256>>>(Wh, Wnode_w, attn_fc_w, rela, Wr, Wqr_w, Wqr_b,
                         q_rel, nrel, batch);

    // K1: init scratch + output
    k_init<<<4096, 256>>>(out, n_node * 64, out_size);

    // K2: edge messages + segment max
    k_edge1<<<2368, 256>>>(hidden, rela, Ws, walpha_w, walpha_b, edges, n_edge);

    // K3: fused node GEMM (node_msg, s0, s1)
    k_gemm<<<(n_node + 127) / 128, 256, GEMM_SMEM>>>(n_node, Wnode_b);

    // K4/K5: softmax statistics
    k_score<<<(n_edge + 255) / 256, 256>>>(edges, attn_fc_b, n_edge);
    k_expsum<<<(n_edge + 255) / 256, 256>>>(n_edge);

    // K6: weighted scatter to output (16 threads/edge, RED.128)
    k_final<<<(n_edge * 16 + 255) / 256, 256>>>(edges, out, n_edge);
}

// round 5
// speedup vs baseline: 1.2331x; 1.0409x over previous
#include <cuda_runtime.h>
#include <cfloat>
#include <cstdint>

// ---------------------------------------------------------------------------
// Problem-size constants
// ---------------------------------------------------------------------------
#define N_NODE_MAX 500000
#define N_EDGE_MAX 1000000
#define NREL_MAX   512
#define BATCH_MAX  64

#define SCAN_TPB   256
#define SCAN_EPT   16
#define SCAN_CHUNK 4096                 // SCAN_TPB * SCAN_EPT
#define NB_MAX     128                  // ceil(N_NODE_MAX/4096)=123

// ---------------------------------------------------------------------------
// Device scratch
// ---------------------------------------------------------------------------
__device__ float    g_agg[(size_t)N_NODE_MAX * 64];      // segment-max result (plain)
__device__ float    g_node_msg[(size_t)N_NODE_MAX * 64]; // agg@M + Wnode_b
__device__ float    g_s0[N_NODE_MAX];
__device__ float    g_s1[N_NODE_MAX];
__device__ float    g_scores[N_EDGE_MAX];
__device__ float    g_Mext[64 * 66];
__device__ float    g_crel[NREL_MAX * 8];
__device__ float    g_cq[BATCH_MAX * 8];
__device__ unsigned g_max_enc;
__device__ float    g_sum;

// counting-sort scratch
__device__ int      g_hist[N_NODE_MAX];
__device__ int      g_off[N_NODE_MAX + 1];
__device__ int      g_cursor[N_NODE_MAX];
__device__ int      g_bsum[NB_MAX];
__device__ int      g_esub[N_EDGE_MAX];
__device__ unsigned g_emeta[N_EDGE_MAX];   // rel | (r_idx<<16)
__device__ int      g_eobj[N_EDGE_MAX];

// ---------------------------------------------------------------------------
// Order-preserving float <-> uint encoding (only for the global score max)
// ---------------------------------------------------------------------------
__device__ __forceinline__ unsigned encf(float x) {
    unsigned u = __float_as_uint(x);
    return (u & 0x80000000u) ? ~u : (u | 0x80000000u);
}
__device__ __forceinline__ float decf(unsigned u) {
    return (u & 0x80000000u) ? __uint_as_float(u & 0x7FFFFFFFu)
                             : __uint_as_float(~u);
}

// ---------------------------------------------------------------------------
// Packed f32x2 helpers
// ---------------------------------------------------------------------------
__device__ __forceinline__ unsigned long long pack2(float a) {
    unsigned long long r;
    asm("mov.b64 %0, {%1, %1};" : "=l"(r) : "r"(__float_as_uint(a)));
    return r;
}
__device__ __forceinline__ void ffma2(unsigned long long& d,
                                      unsigned long long a,
                                      unsigned long long b) {
    asm("fma.rn.f32x2 %0, %1, %2, %0;" : "+l"(d) : "l"(a), "l"(b));
}
__device__ __forceinline__ float2 unpack2(unsigned long long v) {
    unsigned lo, hi;
    asm("mov.b64 {%0, %1}, %2;" : "=r"(lo), "=r"(hi) : "l"(v));
    return make_float2(__uint_as_float(lo), __uint_as_float(hi));
}

// ---------------------------------------------------------------------------
// K0: setup — precompute M_ext = [Wh@Wnode | Wh@w0 | Wh@w1], crel, cq
// ---------------------------------------------------------------------------
__global__ void k_setup(const float* __restrict__ Wh,
                        const float* __restrict__ Wnode,
                        const float* __restrict__ attn_w,
                        const float* __restrict__ rela,
                        const float* __restrict__ Wr,
                        const float* __restrict__ Wqr_w,
                        const float* __restrict__ Wqr_b,
                        const int*   __restrict__ q_rel,
                        int nrel, int batch)
{
    int gtid   = blockIdx.x * blockDim.x + threadIdx.x;
    int stride = gridDim.x * blockDim.x;

    for (int i = gtid; i < 64 * 66; i += stride) {
        int k = i / 66, c = i % 66;
        float s = 0.f;
        if (c < 64) {
            #pragma unroll 8
            for (int j = 0; j < 64; j++) s += Wh[k * 64 + j] * Wnode[j * 64 + c];
        } else {
            const float* w = attn_w + (c - 64) * 64;
            #pragma unroll 8
            for (int j = 0; j < 64; j++) s += Wh[k * 64 + j] * w[j];
        }
        g_Mext[i] = s;
    }
    for (int i = gtid; i < nrel * 5; i += stride) {
        int r = i / 5, j = i % 5;
        float s = 0.f;
        #pragma unroll 8
        for (int k = 0; k < 64; k++) s += rela[r * 64 + k] * Wr[k * 5 + j];
        g_crel[r * 8 + j] = s;
    }
    for (int i = gtid; i < batch * 5; i += stride) {
        int b = i / 5, j = i % 5;
        int qr = q_rel[b];
        float s = Wqr_b[j];
        #pragma unroll 8
        for (int k = 0; k < 64; k++) s += rela[qr * 64 + k] * Wqr_w[k * 5 + j];
        g_cq[b * 8 + j] = s;
    }
}

// ---------------------------------------------------------------------------
// K1: init — out := 0, hist := 0, scalars
// ---------------------------------------------------------------------------
__global__ void k_init(float* __restrict__ out, int out_elems, int n_node)
{
    size_t i      = (size_t)blockIdx.x * blockDim.x + threadIdx.x;
    size_t stride = (size_t)gridDim.x * blockDim.x;

    float4* op = reinterpret_cast<float4*>(out);
    size_t  no = (size_t)out_elems >> 2;
    float4  zv = make_float4(0.f, 0.f, 0.f, 0.f);
    for (size_t t = i; t < no; t += stride) op[t] = zv;

    for (size_t t = i; t < (size_t)n_node; t += stride) g_hist[t] = 0;
    if (i == 0) { g_max_enc = 0u; g_sum = 0.f; }
}

// ---------------------------------------------------------------------------
// K2a: histogram over obj
// ---------------------------------------------------------------------------
__global__ void __launch_bounds__(256)
k_hist(const int* __restrict__ edges, int n_edge)
{
    int e = blockIdx.x * 256 + threadIdx.x;
    if (e < n_edge) atomicAdd(&g_hist[edges[(size_t)e * 6 + 5]], 1);
}

// ---------------------------------------------------------------------------
// K2b/c/d: exclusive scan of g_hist -> g_off (+cursor copy)
// ---------------------------------------------------------------------------
__global__ void __launch_bounds__(SCAN_TPB)
k_scan_block(int n)
{
    __shared__ int wsum[8];
    const int tid  = threadIdx.x;
    const int base = blockIdx.x * SCAN_CHUNK + tid * SCAN_EPT;

    int v[SCAN_EPT];
    int s = 0;
    #pragma unroll
    for (int i = 0; i < SCAN_EPT; i++) {
        int idx = base + i;
        v[i] = (idx < n) ? g_hist[idx] : 0;
        s += v[i];
    }
    const int lane = tid & 31, wid = tid >> 5;
    int inc = s;
    #pragma unroll
    for (int off = 1; off < 32; off <<= 1) {
        int t = __shfl_up_sync(0xFFFFFFFFu, inc, off);
        if (lane >= off) inc += t;
    }
    if (lane == 31) wsum[wid] = inc;
    __syncthreads();
    if (wid == 0) {
        int ws = (lane < 8) ? wsum[lane] : 0;
        #pragma unroll
        for (int off = 1; off < 8; off <<= 1) {
            int t = __shfl_up_sync(0xFFFFFFFFu, ws, off);
            if (lane >= off) ws += t;
        }
        if (lane < 8) wsum[lane] = ws;      // inclusive warp totals
    }
    __syncthreads();
    int run = inc - s + (wid > 0 ? wsum[wid - 1] : 0);
    #pragma unroll
    for (int i = 0; i < SCAN_EPT; i++) {
        int idx = base + i;
        if (idx < n) g_off[idx] = run;
        run += v[i];
    }
    if (tid == SCAN_TPB - 1) g_bsum[blockIdx.x] = run;   // block total
}

__global__ void k_scan_top(int nb)
{
    __shared__ int sh[NB_MAX];
    int t = threadIdx.x;                  // 128 threads
    int v = (t < nb) ? g_bsum[t] : 0;
    sh[t] = v;
    __syncthreads();
    #pragma unroll
    for (int off = 1; off < NB_MAX; off <<= 1) {
        int a = (t >= off) ? sh[t - off] : 0;
        __syncthreads();
        sh[t] += a;
        __syncthreads();
    }
    if (t < nb) g_bsum[t] = sh[t] - v;    // exclusive
}

__global__ void k_scan_add(int n, int n_edge)
{
    int i = blockIdx.x * 256 + threadIdx.x;
    if (i < n) {
        int o = g_off[i] + g_bsum[i >> 12];
        g_off[i]    = o;
        g_cursor[i] = o;
    }
    if (i == n) g_off[n] = n_edge;
}

// ---------------------------------------------------------------------------
// K2e: scatter edges into obj-grouped compact arrays
// ---------------------------------------------------------------------------
__global__ void __launch_bounds__(256)
k_scatter(const int* __restrict__ edges, int n_edge)
{
    int e = blockIdx.x * 256 + threadIdx.x;
    if (e >= n_edge) return;
    const int* ep = edges + (size_t)e * 6;
    int r_idx = ep[0];
    int rel   = ep[2];
    int sub   = ep[4];
    int obj   = ep[5];
    int pos = atomicAdd(&g_cursor[obj], 1);
    g_esub[pos]  = sub;
    g_emeta[pos] = (unsigned)rel | ((unsigned)r_idx << 16);
    g_eobj[pos]  = obj;
}

// ---------------------------------------------------------------------------
// K3: edge messages + segment max — warp per node, NO atomics
// ---------------------------------------------------------------------------
__global__ void __launch_bounds__(256)
k_edge2(const float* __restrict__ hidden,
        const float* __restrict__ rela,
        const float* __restrict__ Ws,       // (64,5)
        const float* __restrict__ wa,       // (5,1)
        const float* __restrict__ wab,      // (1,)
        int n_node)
{
    const int lane = threadIdx.x & 31;

    float wsa[5], wsb[5], wal[5];
    #pragma unroll
    for (int j = 0; j < 5; j++) {
        wsa[j] = __ldg(Ws + (2 * lane) * 5 + j);
        wsb[j] = __ldg(Ws + (2 * lane + 1) * 5 + j);
        wal[j] = __ldg(wa + j);
    }
    const float walb = __ldg(wab);

    const int warps_total = gridDim.x * (blockDim.x >> 5);
    int w = blockIdx.x * (blockDim.x >> 5) + (threadIdx.x >> 5);

    for (int node = w; node < n_node; node += warps_total) {
        const int start = g_off[node];
        const int end   = g_off[node + 1];

        float m0 = -FLT_MAX, m1 = -FLT_MAX;
        for (int i = start; i < end; i++) {
            const int      sub  = g_esub[i];
            const unsigned meta = g_emeta[i];
            const int rel   = meta & 0xFFFFu;
            const int r_idx = meta >> 16;

            const float2 hs = *reinterpret_cast<const float2*>(hidden + (size_t)sub * 64 + 2 * lane);
            const float2 hr = *reinterpret_cast<const float2*>(rela   + (size_t)rel * 64 + 2 * lane);

            float p0 = hs.x * wsa[0] + hs.y * wsb[0];
            float p1 = hs.x * wsa[1] + hs.y * wsb[1];
            float p2 = hs.x * wsa[2] + hs.y * wsb[2];
            float p3 = hs.x * wsa[3] + hs.y * wsb[3];
            float p4 = hs.x * wsa[4] + hs.y * wsb[4];
            #pragma unroll
            for (int off = 16; off > 0; off >>= 1) {
                p0 += __shfl_xor_sync(0xFFFFFFFFu, p0, off);
                p1 += __shfl_xor_sync(0xFFFFFFFFu, p1, off);
                p2 += __shfl_xor_sync(0xFFFFFFFFu, p2, off);
                p3 += __shfl_xor_sync(0xFFFFFFFFu, p3, off);
                p4 += __shfl_xor_sync(0xFFFFFFFFu, p4, off);
            }

            const float4 c4 = *reinterpret_cast<const float4*>(g_crel + rel * 8);
            const float  c5 = g_crel[rel * 8 + 4];
            const float4 q4 = *reinterpret_cast<const float4*>(g_cq + r_idx * 8);
            const float  q5 = g_cq[r_idx * 8 + 4];

            float z = walb;
            z += fmaxf(p0 + c4.x + q4.x, 0.f) * wal[0];
            z += fmaxf(p1 + c4.y + q4.y, 0.f) * wal[1];
            z += fmaxf(p2 + c4.z + q4.z, 0.f) * wal[2];
            z += fmaxf(p3 + c4.w + q4.w, 0.f) * wal[3];
            z += fmaxf(p4 + c5   + q5,   0.f) * wal[4];
            const float alpha = 1.f / (1.f + expf(-z));

            m0 = fmaxf(m0, alpha * (hs.x - hr.x));
            m1 = fmaxf(m1, alpha * (hs.y - hr.y));
        }

        float2 o = (end > start) ? make_float2(m0, m1) : make_float2(0.f, 0.f);
        *reinterpret_cast<float2*>(g_agg + (size_t)node * 64 + 2 * lane) = o;
    }
}

// ---------------------------------------------------------------------------
// K4: node GEMM — node_msg = agg@M + Wnode_b; s0 = agg·v0; s1 = agg·v1
// ---------------------------------------------------------------------------
#define AS_STRIDE 68
#define GEMM_SMEM ((128 * AS_STRIDE + 64 * 64 + 128) * 4)

__global__ void __launch_bounds__(256, 4)
k_gemm(int n_node, const float* __restrict__ Wnode_b)
{
    extern __shared__ float smem[];
    float* As  = smem;                        // 128 * 68
    float* MsL = smem + 128 * AS_STRIDE;      // 64 * 64, [k][half][tx][4]
    float* Vs  = MsL + 64 * 64;               // 64 * 2, [k][{v0,v1}]

    const int tid = threadIdx.x;
    for (int i = tid; i < 64 * 66; i += 256) {
        int k = i / 66, c = i % 66;
        float v = g_Mext[i];
        if (c < 64)
            MsL[k * 64 + ((c & 4) ? 32 : 0) + (c >> 3) * 4 + (c & 3)] = v;
        else
            Vs[k * 2 + (c - 64)] = v;
    }

    const int rb = blockIdx.x * 128;
    const float4* src = reinterpret_cast<const float4*>(g_agg + (size_t)rb * 64);
    const bool full = (rb + 128 <= n_node);

    #pragma unroll
    for (int t = 0; t < 8; t++) {
        int vidx = tid + t * 256;
        int r  = vidx >> 4;
        int k4 = (vidx & 15) * 4;
        float4 u = make_float4(0.f, 0.f, 0.f, 0.f);
        if (full || rb + r < n_node) u = src[vidx];
        *reinterpret_cast<float4*>(As + r * AS_STRIDE + k4) = u;
    }
    __syncthreads();

    const int tx = tid & 7;
    const int ty = tid >> 3;

    unsigned long long acc[4][4];
    #pragma unroll
    for (int i = 0; i < 4; i++)
        #pragma unroll
        for (int c = 0; c < 4; c++) acc[i][c] = 0ull;

    const float* arow  = As + ty * 4 * AS_STRIDE;
    const float* mbase = MsL + tx * 4;

    #pragma unroll 2
    for (int k4 = 0; k4 < 64; k4 += 4) {
        float4 a[4];
        #pragma unroll
        for (int i = 0; i < 4; i++)
            a[i] = *reinterpret_cast<const float4*>(arow + i * AS_STRIDE + k4);

        #pragma unroll
        for (int kk = 0; kk < 4; kk++) {
            const ulonglong2 mp0 = *reinterpret_cast<const ulonglong2*>(mbase + (k4 + kk) * 64);
            const ulonglong2 mp1 = *reinterpret_cast<const ulonglong2*>(mbase + (k4 + kk) * 64 + 32);
            #pragma unroll
            for (int i = 0; i < 4; i++) {
                const float av = (kk == 0) ? a[i].x : (kk == 1) ? a[i].y
                               : (kk == 2) ? a[i].z : a[i].w;
                const unsigned long long aa = pack2(av);
                ffma2(acc[i][0], aa, mp0.x);
                ffma2(acc[i][1], aa, mp0.y);
                ffma2(acc[i][2], aa, mp1.x);
                ffma2(acc[i][3], aa, mp1.y);
            }
        }
    }

    const float4 b0 = *reinterpret_cast<const float4*>(Wnode_b + tx * 8);
    const float4 b1 = *reinterpret_cast<const float4*>(Wnode_b + tx * 8 + 4);
    #pragma unroll
    for (int i = 0; i < 4; i++) {
        int grow = rb + ty * 4 + i;
        if (grow < n_node) {
            float2 a0 = unpack2(acc[i][0]);
            float2 a1 = unpack2(acc[i][1]);
            float2 a2 = unpack2(acc[i][2]);
            float2 a3 = unpack2(acc[i][3]);
            float* op = g_node_msg + (size_t)grow * 64 + tx * 8;
            *reinterpret_cast<float4*>(op) =
                make_float4(a0.x + b0.x, a0.y + b0.y, a1.x + b0.z, a1.y + b0.w);
            *reinterpret_cast<float4*>(op + 4) =
                make_float4(a2.x + b1.x, a2.y + b1.y, a3.x + b1.z, a3.y + b1.w);
        }
    }

    if (tid < 128) {
        int grow = rb + tid;
        if (grow < n_node) {
            unsigned long long s01 = 0ull;
            const float* ar = As + tid * AS_STRIDE;
            #pragma unroll 8
            for (int k = 0; k < 64; k++) {
                const unsigned long long v01 =
                    *reinterpret_cast<const unsigned long long*>(Vs + k * 2);
                ffma2(s01, pack2(ar[k]), v01);
            }
            float2 s = unpack2(s01);
            g_s0[grow] = s.x;
            g_s1[grow] = s.y;
        }
    }
}

// ---------------------------------------------------------------------------
// K5: edge scores + global max (sorted-edge order)
// ---------------------------------------------------------------------------
__global__ void __launch_bounds__(256)
k_score(const float* __restrict__ attn_b, int n_edge)
{
    const int e = blockIdx.x * 256 + threadIdx.x;
    float sc = -FLT_MAX;
    if (e < n_edge) {
        float s = g_s0[g_esub[e]] + g_s1[g_eobj[e]] + __ldg(attn_b);
        sc = (s > 0.f) ? s : 0.2f * s;
        g_scores[e] = sc;
    }
    __shared__ float red[8];
    const int lane = threadIdx.x & 31, wid = threadIdx.x >> 5;
    #pragma unroll
    for (int off = 16; off > 0; off >>= 1)
        sc = fmaxf(sc, __shfl_xor_sync(0xFFFFFFFFu, sc, off));
    if (lane == 0) red[wid] = sc;
    __syncthreads();
    if (wid == 0) {
        float v = (lane < 8) ? red[lane] : -FLT_MAX;
        #pragma unroll
        for (int off = 4; off > 0; off >>= 1)
            v = fmaxf(v, __shfl_xor_sync(0xFFFFFFFFu, v, off));
        if (lane == 0) atomicMax(&g_max_enc, encf(v));
    }
}

// ---------------------------------------------------------------------------
// K6: exp(score - max) in place + global sum
// ---------------------------------------------------------------------------
__global__ void __launch_bounds__(256)
k_expsum(int n_edge)
{
    const float gm = decf(g_max_enc);
    const int e = blockIdx.x * 256 + threadIdx.x;
    float v = 0.f;
    if (e < n_edge) {
        v = expf(g_scores[e] - gm);
        g_scores[e] = v;
    }
    __shared__ float red[8];
    const int lane = threadIdx.x & 31, wid = threadIdx.x >> 5;
    #pragma unroll
    for (int off = 16; off > 0; off >>= 1)
        v += __shfl_xor_sync(0xFFFFFFFFu, v, off);
    if (lane == 0) red[wid] = v;
    __syncthreads();
    if (wid == 0) {
        float s = (lane < 8) ? red[lane] : 0.f;
        #pragma unroll
        for (int off = 4; off > 0; off >>= 1)
            s += __shfl_xor_sync(0xFFFFFFFFu, s, off);
        if (lane == 0) atomicAdd(&g_sum, s);
    }
}

// ---------------------------------------------------------------------------
// K7: final weighted scatter — out[sub] += w_e * node_msg[obj]
// ---------------------------------------------------------------------------
__global__ void __launch_bounds__(256)
k_final(float* __restrict__ out, int n_edge)
{
    const float inv = 1.f / g_sum;
    const int t = blockIdx.x * 256 + threadIdx.x;
    const int e = t >> 4;
    const int q = t & 15;
    if (e >= n_edge) return;

    const int sub = g_esub[e];
    const int obj = g_eobj[e];
    const float wgt = g_scores[e] * inv;
    const float4 m = *reinterpret_cast<const float4*>(
        g_node_msg + (size_t)obj * 64 + q * 4);
    float* op = out + (size_t)sub * 64 + q * 4;
    asm volatile("red.global.add.v4.f32 [%0], {%1, %2, %3, %4};"
                 :: "l"(op), "f"(wgt * m.x), "f"(wgt * m.y),
                    "f"(wgt * m.z), "f"(wgt * m.w)
                 : "memory");
}

// ---------------------------------------------------------------------------
// kernel_launch
// ---------------------------------------------------------------------------
extern "C" void kernel_launch(void* const* d_in, const int* in_sizes, int n_in,
                              void* d_out, int out_size)
{
    const float* hidden    = (const float*)d_in[0];
    const float* rela      = (const float*)d_in[1];
    const float* Ws        = (const float*)d_in[2];
    const float* Wr        = (const float*)d_in[3];
    const float* Wqr_w     = (const float*)d_in[4];
    const float* Wqr_b     = (const float*)d_in[5];
    const float* walpha_w  = (const float*)d_in[6];
    const float* walpha_b  = (const float*)d_in[7];
    const float* Wh        = (const float*)d_in[8];
    const float* attn_fc_w = (const float*)d_in[9];
    const float* attn_fc_b = (const float*)d_in[10];
    const float* Wnode_w   = (const float*)d_in[11];
    const float* Wnode_b   = (const float*)d_in[12];
    const int*   q_rel     = (const int*)d_in[14];
    const int*   edges     = (const int*)d_in[15];
    float*       out       = (float*)d_out;

    const int n_edge = in_sizes[15] / 6;
    const int n_node = in_sizes[16] / 2;
    const int nrel   = in_sizes[1] / 64;
    const int batch  = in_sizes[14];
    const int nb     = (n_node + SCAN_CHUNK - 1) / SCAN_CHUNK;

    static bool attr_set = false;
    if (!attr_set) {
        cudaFuncSetAttribute(k_gemm, cudaFuncAttributeMaxDynamicSharedMemorySize,
                             GEMM_SMEM);
        attr_set = true;
    }

    // precompute small tables
    k_setup<<<32, 256>>>(Wh, Wnode_w, attn_fc_w, rela, Wr, Wqr_w, Wqr_b,
                         q_rel, nrel, batch);

    // init out + hist + scalars
    k_init<<<4096, 256>>>(out, out_size, n_node);

    // counting sort of edges by obj
    k_hist<<<(n_edge + 255) / 256, 256>>>(edges, n_edge);
    k_scan_block<<<nb, SCAN_TPB>>>(n_node);
    k_scan_top<<<1, NB_MAX>>>(nb);
    k_scan_add<<<(n_node + 256) / 256, 256>>>(n_node, n_edge);
    k_scatter<<<(n_edge + 255) / 256, 256>>>(edges, n_edge);

    // edge messages + segment max (warp per node, no atomics)
    k_edge2<<<2368, 256>>>(hidden, rela, Ws, walpha_w, walpha_b, n_node);

    // fused node GEMM
    k_gemm<<<(n_node + 127) / 128, 256, GEMM_SMEM>>>(n_node, Wnode_b);

    // softmax statistics
    k_score<<<(n_edge + 255) / 256, 256>>>(attn_fc_b, n_edge);
    k_expsum<<<(n_edge + 255) / 256, 256>>>(n_edge);

    // weighted scatter to output
    k_final<<<(n_edge * 16 + 255) / 256, 256>>>(out, n_edge);
}

// round 6
// speedup vs baseline: 1.3991x; 1.1346x over previous
#include <cuda_runtime.h>
#include <cfloat>
#include <cstdint>

// ---------------------------------------------------------------------------
// Problem-size constants
// ---------------------------------------------------------------------------
#define N_NODE_MAX 500000
#define N_EDGE_MAX 1000000
#define NREL_MAX   512
#define BATCH_MAX  64

#define SCAN_TPB   256
#define SCAN_EPT   16
#define SCAN_CHUNK 4096
#define NB_MAX     128

// ---------------------------------------------------------------------------
// Device scratch
// ---------------------------------------------------------------------------
__device__ float    g_agg[(size_t)N_NODE_MAX * 64];
__device__ float    g_node_msg[(size_t)N_NODE_MAX * 64];
__device__ float    g_h5[(size_t)N_NODE_MAX * 8];        // hidden@Ws (padded)
__device__ float    g_alpha[N_EDGE_MAX];
__device__ float    g_s0[N_NODE_MAX];
__device__ float    g_s1[N_NODE_MAX];
__device__ float    g_scores[N_EDGE_MAX];
__device__ float    g_Mext[64 * 66];
__device__ float    g_crel[NREL_MAX * 8];
__device__ float    g_cq[BATCH_MAX * 8];
__device__ unsigned g_max_enc;
__device__ float    g_sum;

// counting-sort scratch
__device__ int      g_hist[N_NODE_MAX];
__device__ int      g_off[N_NODE_MAX + 1];
__device__ int      g_cursor[N_NODE_MAX];
__device__ int      g_bsum[NB_MAX];
__device__ int      g_esub[N_EDGE_MAX];
__device__ unsigned g_emeta[N_EDGE_MAX];   // rel | (r_idx<<16)
__device__ int      g_eobj[N_EDGE_MAX];

// ---------------------------------------------------------------------------
// Order-preserving float <-> uint encoding
// ---------------------------------------------------------------------------
__device__ __forceinline__ unsigned encf(float x) {
    unsigned u = __float_as_uint(x);
    return (u & 0x80000000u) ? ~u : (u | 0x80000000u);
}
__device__ __forceinline__ float decf(unsigned u) {
    return (u & 0x80000000u) ? __uint_as_float(u & 0x7FFFFFFFu)
                             : __uint_as_float(~u);
}

// ---------------------------------------------------------------------------
// Packed f32x2 helpers
// ---------------------------------------------------------------------------
__device__ __forceinline__ unsigned long long pack2(float a) {
    unsigned long long r;
    asm("mov.b64 %0, {%1, %1};" : "=l"(r) : "r"(__float_as_uint(a)));
    return r;
}
__device__ __forceinline__ void ffma2(unsigned long long& d,
                                      unsigned long long a,
                                      unsigned long long b) {
    asm("fma.rn.f32x2 %0, %1, %2, %0;" : "+l"(d) : "l"(a), "l"(b));
}
__device__ __forceinline__ float2 unpack2(unsigned long long v) {
    unsigned lo, hi;
    asm("mov.b64 {%0, %1}, %2;" : "=r"(lo), "=r"(hi) : "l"(v));
    return make_float2(__uint_as_float(lo), __uint_as_float(hi));
}

// ---------------------------------------------------------------------------
// K0: setup — M_ext = [Wh@Wnode | Wh@w0 | Wh@w1], crel, cq
// ---------------------------------------------------------------------------
__global__ void k_setup(const float* __restrict__ Wh,
                        const float* __restrict__ Wnode,
                        const float* __restrict__ attn_w,
                        const float* __restrict__ rela,
                        const float* __restrict__ Wr,
                        const float* __restrict__ Wqr_w,
                        const float* __restrict__ Wqr_b,
                        const int*   __restrict__ q_rel,
                        int nrel, int batch)
{
    int gtid   = blockIdx.x * blockDim.x + threadIdx.x;
    int stride = gridDim.x * blockDim.x;

    for (int i = gtid; i < 64 * 66; i += stride) {
        int k = i / 66, c = i % 66;
        float s = 0.f;
        if (c < 64) {
            #pragma unroll 8
            for (int j = 0; j < 64; j++) s += Wh[k * 64 + j] * Wnode[j * 64 + c];
        } else {
            const float* w = attn_w + (c - 64) * 64;
            #pragma unroll 8
            for (int j = 0; j < 64; j++) s += Wh[k * 64 + j] * w[j];
        }
        g_Mext[i] = s;
    }
    for (int i = gtid; i < nrel * 5; i += stride) {
        int r = i / 5, j = i % 5;
        float s = 0.f;
        #pragma unroll 8
        for (int k = 0; k < 64; k++) s += rela[r * 64 + k] * Wr[k * 5 + j];
        g_crel[r * 8 + j] = s;
    }
    for (int i = gtid; i < batch * 5; i += stride) {
        int b = i / 5, j = i % 5;
        int qr = q_rel[b];
        float s = Wqr_b[j];
        #pragma unroll 8
        for (int k = 0; k < 64; k++) s += rela[qr * 64 + k] * Wqr_w[k * 5 + j];
        g_cq[b * 8 + j] = s;
    }
}

// ---------------------------------------------------------------------------
// K1: init — out := 0, hist := 0, scalars
// ---------------------------------------------------------------------------
__global__ void k_init(float* __restrict__ out, int out_elems, int n_node)
{
    size_t i      = (size_t)blockIdx.x * blockDim.x + threadIdx.x;
    size_t stride = (size_t)gridDim.x * blockDim.x;

    float4* op = reinterpret_cast<float4*>(out);
    size_t  no = (size_t)out_elems >> 2;
    float4  zv = make_float4(0.f, 0.f, 0.f, 0.f);
    for (size_t t = i; t < no; t += stride) op[t] = zv;

    for (size_t t = i; t < (size_t)n_node; t += stride) g_hist[t] = 0;
    if (i == 0) { g_max_enc = 0u; g_sum = 0.f; }
}

// ---------------------------------------------------------------------------
// K2a: histogram over obj
// ---------------------------------------------------------------------------
__global__ void __launch_bounds__(256)
k_hist(const int* __restrict__ edges, int n_edge)
{
    int e = blockIdx.x * 256 + threadIdx.x;
    if (e < n_edge) atomicAdd(&g_hist[edges[(size_t)e * 6 + 5]], 1);
}

// ---------------------------------------------------------------------------
// K2b/c/d: exclusive scan of g_hist -> g_off (+cursor copy)
// ---------------------------------------------------------------------------
__global__ void __launch_bounds__(SCAN_TPB)
k_scan_block(int n)
{
    __shared__ int wsum[8];
    const int tid  = threadIdx.x;
    const int base = blockIdx.x * SCAN_CHUNK + tid * SCAN_EPT;

    int v[SCAN_EPT];
    int s = 0;
    #pragma unroll
    for (int i = 0; i < SCAN_EPT; i++) {
        int idx = base + i;
        v[i] = (idx < n) ? g_hist[idx] : 0;
        s += v[i];
    }
    const int lane = tid & 31, wid = tid >> 5;
    int inc = s;
    #pragma unroll
    for (int off = 1; off < 32; off <<= 1) {
        int t = __shfl_up_sync(0xFFFFFFFFu, inc, off);
        if (lane >= off) inc += t;
    }
    if (lane == 31) wsum[wid] = inc;
    __syncthreads();
    if (wid == 0) {
        int ws = (lane < 8) ? wsum[lane] : 0;
        #pragma unroll
        for (int off = 1; off < 8; off <<= 1) {
            int t = __shfl_up_sync(0xFFFFFFFFu, ws, off);
            if (lane >= off) ws += t;
        }
        if (lane < 8) wsum[lane] = ws;
    }
    __syncthreads();
    int run = inc - s + (wid > 0 ? wsum[wid - 1] : 0);
    #pragma unroll
    for (int i = 0; i < SCAN_EPT; i++) {
        int idx = base + i;
        if (idx < n) g_off[idx] = run;
        run += v[i];
    }
    if (tid == SCAN_TPB - 1) g_bsum[blockIdx.x] = run;
}

__global__ void k_scan_top(int nb)
{
    __shared__ int sh[NB_MAX];
    int t = threadIdx.x;
    int v = (t < nb) ? g_bsum[t] : 0;
    sh[t] = v;
    __syncthreads();
    #pragma unroll
    for (int off = 1; off < NB_MAX; off <<= 1) {
        int a = (t >= off) ? sh[t - off] : 0;
        __syncthreads();
        sh[t] += a;
        __syncthreads();
    }
    if (t < nb) g_bsum[t] = sh[t] - v;
}

__global__ void k_scan_add(int n, int n_edge)
{
    int i = blockIdx.x * 256 + threadIdx.x;
    if (i < n) {
        int o = g_off[i] + g_bsum[i >> 12];
        g_off[i]    = o;
        g_cursor[i] = o;
    }
    if (i == n) g_off[n] = n_edge;
}

// ---------------------------------------------------------------------------
// K2e: scatter edges into obj-grouped compact arrays
// ---------------------------------------------------------------------------
__global__ void __launch_bounds__(256)
k_scatter(const int* __restrict__ edges, int n_edge)
{
    int e = blockIdx.x * 256 + threadIdx.x;
    if (e >= n_edge) return;
    const int* ep = edges + (size_t)e * 6;
    int r_idx = ep[0];
    int rel   = ep[2];
    int sub   = ep[4];
    int obj   = ep[5];
    int pos = atomicAdd(&g_cursor[obj], 1);
    g_esub[pos]  = sub;
    g_emeta[pos] = (unsigned)rel | ((unsigned)r_idx << 16);
    g_eobj[pos]  = obj;
}

// ---------------------------------------------------------------------------
// K3a: H5 = hidden @ Ws per node (warp per node), padded stride 8
// ---------------------------------------------------------------------------
__global__ void __launch_bounds__(256)
k_h5(const float* __restrict__ hidden,
     const float* __restrict__ Ws,
     int n_node)
{
    const int lane = threadIdx.x & 31;

    float wsa[5], wsb[5];
    #pragma unroll
    for (int j = 0; j < 5; j++) {
        wsa[j] = __ldg(Ws + (2 * lane) * 5 + j);
        wsb[j] = __ldg(Ws + (2 * lane + 1) * 5 + j);
    }

    const int warps_total = gridDim.x * (blockDim.x >> 5);
    int w = blockIdx.x * (blockDim.x >> 5) + (threadIdx.x >> 5);

    for (int node = w; node < n_node; node += warps_total) {
        const float2 h = *reinterpret_cast<const float2*>(hidden + (size_t)node * 64 + 2 * lane);
        float p0 = h.x * wsa[0] + h.y * wsb[0];
        float p1 = h.x * wsa[1] + h.y * wsb[1];
        float p2 = h.x * wsa[2] + h.y * wsb[2];
        float p3 = h.x * wsa[3] + h.y * wsb[3];
        float p4 = h.x * wsa[4] + h.y * wsb[4];
        #pragma unroll
        for (int off = 16; off > 0; off >>= 1) {
            p0 += __shfl_xor_sync(0xFFFFFFFFu, p0, off);
            p1 += __shfl_xor_sync(0xFFFFFFFFu, p1, off);
            p2 += __shfl_xor_sync(0xFFFFFFFFu, p2, off);
            p3 += __shfl_xor_sync(0xFFFFFFFFu, p3, off);
            p4 += __shfl_xor_sync(0xFFFFFFFFu, p4, off);
        }
        if (lane == 0) {
            float* dst = g_h5 + (size_t)node * 8;
            *reinterpret_cast<float4*>(dst) = make_float4(p0, p1, p2, p3);
            dst[4] = p4;
        }
    }
}

// ---------------------------------------------------------------------------
// K3b: alpha per edge (thread per sorted edge) — H5 table is L2-resident
// ---------------------------------------------------------------------------
__global__ void __launch_bounds__(256)
k_alpha(const float* __restrict__ wa, const float* __restrict__ wab, int n_edge)
{
    const int e = blockIdx.x * 256 + threadIdx.x;
    if (e >= n_edge) return;

    const int      sub  = g_esub[e];
    const unsigned meta = g_emeta[e];
    const int rel   = meta & 0xFFFFu;
    const int r_idx = meta >> 16;

    const float4 h4 = *reinterpret_cast<const float4*>(g_h5 + (size_t)sub * 8);
    const float  h5 = g_h5[(size_t)sub * 8 + 4];
    const float4 c4 = *reinterpret_cast<const float4*>(g_crel + rel * 8);
    const float  c5 = g_crel[rel * 8 + 4];
    const float4 q4 = *reinterpret_cast<const float4*>(g_cq + r_idx * 8);
    const float  q5 = g_cq[r_idx * 8 + 4];

    float z = __ldg(wab);
    z += fmaxf(h4.x + c4.x + q4.x, 0.f) * __ldg(wa + 0);
    z += fmaxf(h4.y + c4.y + q4.y, 0.f) * __ldg(wa + 1);
    z += fmaxf(h4.z + c4.z + q4.z, 0.f) * __ldg(wa + 2);
    z += fmaxf(h4.w + c4.w + q4.w, 0.f) * __ldg(wa + 3);
    z += fmaxf(h5   + c5   + q5,   0.f) * __ldg(wa + 4);
    g_alpha[e] = 1.f / (1.f + expf(-z));
}

// ---------------------------------------------------------------------------
// K3c: segment max — warp per node, lean loop (no shuffles, no transcend.)
// ---------------------------------------------------------------------------
__global__ void __launch_bounds__(256)
k_edge2(const float* __restrict__ hidden,
        const float* __restrict__ rela,
        int n_node)
{
    const int lane = threadIdx.x & 31;
    const int warps_total = gridDim.x * (blockDim.x >> 5);
    int w = blockIdx.x * (blockDim.x >> 5) + (threadIdx.x >> 5);

    for (int node = w; node < n_node; node += warps_total) {
        const int start = g_off[node];
        const int end   = g_off[node + 1];

        float m0 = -FLT_MAX, m1 = -FLT_MAX;
        for (int i = start; i < end; i++) {
            const float    alpha = __ldg(g_alpha + i);
            const int      sub   = g_esub[i];
            const int      rel   = g_emeta[i] & 0xFFFFu;
            const float2 hs = *reinterpret_cast<const float2*>(hidden + (size_t)sub * 64 + 2 * lane);
            const float2 hr = *reinterpret_cast<const float2*>(rela   + (size_t)rel * 64 + 2 * lane);
            m0 = fmaxf(m0, alpha * (hs.x - hr.x));
            m1 = fmaxf(m1, alpha * (hs.y - hr.y));
        }
        float2 o = (end > start) ? make_float2(m0, m1) : make_float2(0.f, 0.f);
        *reinterpret_cast<float2*>(g_agg + (size_t)node * 64 + 2 * lane) = o;
    }
}

// ---------------------------------------------------------------------------
// K4: node GEMM — 256 rows x 64 cols per block, 256 threads, 8x8 thread tile
// ---------------------------------------------------------------------------
#define AS_STRIDE 68
#define GEMM_ROWS 256
#define GEMM_SMEM ((GEMM_ROWS * AS_STRIDE + 64 * 64 + 128) * 4)

__global__ void __launch_bounds__(256, 2)
k_gemm(int n_node, const float* __restrict__ Wnode_b)
{
    extern __shared__ float smem[];
    float* As  = smem;                            // 256 * 68
    float* MsL = smem + GEMM_ROWS * AS_STRIDE;    // 64 * 64, [k][half][tx][4]
    float* Vs  = MsL + 64 * 64;                   // 64 * 2

    const int tid = threadIdx.x;
    for (int i = tid; i < 64 * 66; i += 256) {
        int k = i / 66, c = i % 66;
        float v = g_Mext[i];
        if (c < 64)
            MsL[k * 64 + ((c & 4) ? 32 : 0) + (c >> 3) * 4 + (c & 3)] = v;
        else
            Vs[k * 2 + (c - 64)] = v;
    }

    const int rb = blockIdx.x * GEMM_ROWS;
    const float4* src = reinterpret_cast<const float4*>(g_agg + (size_t)rb * 64);
    const bool full = (rb + GEMM_ROWS <= n_node);

    #pragma unroll
    for (int t = 0; t < 16; t++) {
        int vidx = tid + t * 256;          // float4 index 0..4095
        int r  = vidx >> 4;
        int k4 = (vidx & 15) * 4;
        float4 u = make_float4(0.f, 0.f, 0.f, 0.f);
        if (full || rb + r < n_node) u = src[vidx];
        *reinterpret_cast<float4*>(As + r * AS_STRIDE + k4) = u;
    }
    __syncthreads();

    const int tx = tid & 7;    // 8 col-groups of 8 cols (4 f32x2 pairs)
    const int ty = tid >> 3;   // 32 row-groups of 8 rows

    unsigned long long acc[8][4];
    #pragma unroll
    for (int i = 0; i < 8; i++)
        #pragma unroll
        for (int c = 0; c < 4; c++) acc[i][c] = 0ull;

    const float* arow  = As + ty * 8 * AS_STRIDE;
    const float* mbase = MsL + tx * 4;

    for (int k4 = 0; k4 < 64; k4 += 4) {
        float4 a[8];
        #pragma unroll
        for (int i = 0; i < 8; i++)
            a[i] = *reinterpret_cast<const float4*>(arow + i * AS_STRIDE + k4);

        #pragma unroll
        for (int kk = 0; kk < 4; kk++) {
            const ulonglong2 mp0 = *reinterpret_cast<const ulonglong2*>(mbase + (k4 + kk) * 64);
            const ulonglong2 mp1 = *reinterpret_cast<const ulonglong2*>(mbase + (k4 + kk) * 64 + 32);
            #pragma unroll
            for (int i = 0; i < 8; i++) {
                const float av = (kk == 0) ? a[i].x : (kk == 1) ? a[i].y
                               : (kk == 2) ? a[i].z : a[i].w;
                const unsigned long long aa = pack2(av);
                ffma2(acc[i][0], aa, mp0.x);
                ffma2(acc[i][1], aa, mp0.y);
                ffma2(acc[i][2], aa, mp1.x);
                ffma2(acc[i][3], aa, mp1.y);
            }
        }
    }

    const float4 b0 = *reinterpret_cast<const float4*>(Wnode_b + tx * 8);
    const float4 b1 = *reinterpret_cast<const float4*>(Wnode_b + tx * 8 + 4);
    #pragma unroll
    for (int i = 0; i < 8; i++) {
        int grow = rb + ty * 8 + i;
        if (grow < n_node) {
            float2 a0 = unpack2(acc[i][0]);
            float2 a1 = unpack2(acc[i][1]);
            float2 a2 = unpack2(acc[i][2]);
            float2 a3 = unpack2(acc[i][3]);
            float* op = g_node_msg + (size_t)grow * 64 + tx * 8;
            *reinterpret_cast<float4*>(op) =
                make_float4(a0.x + b0.x, a0.y + b0.y, a1.x + b0.z, a1.y + b0.w);
            *reinterpret_cast<float4*>(op + 4) =
                make_float4(a2.x + b1.x, a2.y + b1.y, a3.x + b1.z, a3.y + b1.w);
        }
    }

    // s0/s1 epilogue: one row per thread (256 rows, 256 threads)
    {
        int grow = rb + tid;
        if (grow < n_node) {
            unsigned long long s01 = 0ull;
            const float* ar = As + tid * AS_STRIDE;
            #pragma unroll 8
            for (int k = 0; k < 64; k++) {
                const unsigned long long v01 =
                    *reinterpret_cast<const unsigned long long*>(Vs + k * 2);
                ffma2(s01, pack2(ar[k]), v01);
            }
            float2 s = unpack2(s01);
            g_s0[grow] = s.x;
            g_s1[grow] = s.y;
        }
    }
}

// ---------------------------------------------------------------------------
// K5: edge scores + global max
// ---------------------------------------------------------------------------
__global__ void __launch_bounds__(256)
k_score(const float* __restrict__ attn_b, int n_edge)
{
    const int e = blockIdx.x * 256 + threadIdx.x;
    float sc = -FLT_MAX;
    if (e < n_edge) {
        float s = g_s0[g_esub[e]] + g_s1[g_eobj[e]] + __ldg(attn_b);
        sc = (s > 0.f) ? s : 0.2f * s;
        g_scores[e] = sc;
    }
    __shared__ float red[8];
    const int lane = threadIdx.x & 31, wid = threadIdx.x >> 5;
    #pragma unroll
    for (int off = 16; off > 0; off >>= 1)
        sc = fmaxf(sc, __shfl_xor_sync(0xFFFFFFFFu, sc, off));
    if (lane == 0) red[wid] = sc;
    __syncthreads();
    if (wid == 0) {
        float v = (lane < 8) ? red[lane] : -FLT_MAX;
        #pragma unroll
        for (int off = 4; off > 0; off >>= 1)
            v = fmaxf(v, __shfl_xor_sync(0xFFFFFFFFu, v, off));
        if (lane == 0) atomicMax(&g_max_enc, encf(v));
    }
}

// ---------------------------------------------------------------------------
// K6: exp(score - max) in place + global sum
// ---------------------------------------------------------------------------
__global__ void __launch_bounds__(256)
k_expsum(int n_edge)
{
    const float gm = decf(g_max_enc);
    const int e = blockIdx.x * 256 + threadIdx.x;
    float v = 0.f;
    if (e < n_edge) {
        v = expf(g_scores[e] - gm);
        g_scores[e] = v;
    }
    __shared__ float red[8];
    const int lane = threadIdx.x & 31, wid = threadIdx.x >> 5;
    #pragma unroll
    for (int off = 16; off > 0; off >>= 1)
        v += __shfl_xor_sync(0xFFFFFFFFu, v, off);
    if (lane == 0) red[wid] = v;
    __syncthreads();
    if (wid == 0) {
        float s = (lane < 8) ? red[lane] : 0.f;
        #pragma unroll
        for (int off = 4; off > 0; off >>= 1)
            s += __shfl_xor_sync(0xFFFFFFFFu, s, off);
        if (lane == 0) atomicAdd(&g_sum, s);
    }
}

// ---------------------------------------------------------------------------
// K7: final weighted scatter — out[sub] += w_e * node_msg[obj]
// ---------------------------------------------------------------------------
__global__ void __launch_bounds__(256)
k_final(float* __restrict__ out, int n_edge)
{
    const float inv = 1.f / g_sum;
    const int t = blockIdx.x * 256 + threadIdx.x;
    const int e = t >> 4;
    const int q = t & 15;
    if (e >= n_edge) return;

    const int sub = g_esub[e];
    const int obj = g_eobj[e];
    const float wgt = g_scores[e] * inv;
    const float4 m = *reinterpret_cast<const float4*>(
        g_node_msg + (size_t)obj * 64 + q * 4);
    float* op = out + (size_t)sub * 64 + q * 4;
    asm volatile("red.global.add.v4.f32 [%0], {%1, %2, %3, %4};"
                 :: "l"(op), "f"(wgt * m.x), "f"(wgt * m.y),
                    "f"(wgt * m.z), "f"(wgt * m.w)
                 : "memory");
}

// ---------------------------------------------------------------------------
// kernel_launch
// ---------------------------------------------------------------------------
extern "C" void kernel_launch(void* const* d_in, const int* in_sizes, int n_in,
                              void* d_out, int out_size)
{
    const float* hidden    = (const float*)d_in[0];
    const float* rela      = (const float*)d_in[1];
    const float* Ws        = (const float*)d_in[2];
    const float* Wr        = (const float*)d_in[3];
    const float* Wqr_w     = (const float*)d_in[4];
    const float* Wqr_b     = (const float*)d_in[5];
    const float* walpha_w  = (const float*)d_in[6];
    const float* walpha_b  = (const float*)d_in[7];
    const float* Wh        = (const float*)d_in[8];
    const float* attn_fc_w = (const float*)d_in[9];
    const float* attn_fc_b = (const float*)d_in[10];
    const float* Wnode_w   = (const float*)d_in[11];
    const float* Wnode_b   = (const float*)d_in[12];
    const int*   q_rel     = (const int*)d_in[14];
    const int*   edges     = (const int*)d_in[15];
    float*       out       = (float*)d_out;

    const int n_edge = in_sizes[15] / 6;
    const int n_node = in_sizes[16] / 2;
    const int nrel   = in_sizes[1] / 64;
    const int batch  = in_sizes[14];
    const int nb     = (n_node + SCAN_CHUNK - 1) / SCAN_CHUNK;

    static bool attr_set = false;
    if (!attr_set) {
        cudaFuncSetAttribute(k_gemm, cudaFuncAttributeMaxDynamicSharedMemorySize,
                             GEMM_SMEM);
        attr_set = true;
    }

    // small tables
    k_setup<<<32, 256>>>(Wh, Wnode_w, attn_fc_w, rela, Wr, Wqr_w, Wqr_b,
                         q_rel, nrel, batch);

    // init out + hist + scalars
    k_init<<<4096, 256>>>(out, out_size, n_node);

    // counting sort of edges by obj
    k_hist<<<(n_edge + 255) / 256, 256>>>(edges, n_edge);
    k_scan_block<<<nb, SCAN_TPB>>>(n_node);
    k_scan_top<<<1, NB_MAX>>>(nb);
    k_scan_add<<<(n_node + 256) / 256, 256>>>(n_node, n_edge);
    k_scatter<<<(n_edge + 255) / 256, 256>>>(edges, n_edge);

    // attention precompute
    k_h5<<<2368, 256>>>(hidden, Ws, n_node);
    k_alpha<<<(n_edge + 255) / 256, 256>>>(walpha_w, walpha_b, n_edge);

    // segment max (warp per node, lean loop)
    k_edge2<<<2368, 256>>>(hidden, rela, n_node);

    // fused node GEMM (8x8 thread tile)
    k_gemm<<<(n_node + GEMM_ROWS - 1) / GEMM_ROWS, 256, GEMM_SMEM>>>(n_node, Wnode_b);

    // softmax statistics
    k_score<<<(n_edge + 255) / 256, 256>>>(attn_fc_b, n_edge);
    k_expsum<<<(n_edge + 255) / 256, 256>>>(n_edge);

    // weighted scatter to output
    k_final<<<(n_edge * 16 + 255) / 256, 256>>>(out, n_edge);
}